// round 2
// baseline (speedup 1.0000x reference)
#include <cuda_runtime.h>
#include <math.h>

// Problem dims (fixed per reference)
#define BB 4
#define SS 2048
#define DD 768
#define UU 768

// ---------------- scratch (no allocations allowed) ----------------
__device__ float g_Q[(size_t)BB * SS * UU];
__device__ float g_K[(size_t)BB * SS * UU];
__device__ float g_V[(size_t)BB * SS * UU];
__device__ float g_S[(size_t)BB * SS * SS];

// ---------------- tiled SGEMM ----------------
// C[M,N] = alpha * A[M,K] * op(B)      op(B) = B[K,N] (NN) or B[N,K]^T (NT)
// 64x64 block tile, BK=16, 256 threads, 4x4 per-thread micro-tile.
#define BM 64
#define BN 64
#define BKT 16

template <bool TRANSB>
__global__ __launch_bounds__(256) void sgemm_kernel(
    const float* __restrict__ A, const float* __restrict__ Bm,
    float* __restrict__ C,
    int M, int N, int K,
    size_t strideA, size_t strideB, size_t strideC,
    float alpha)
{
    __shared__ float As[BKT][BM + 4];
    __shared__ float Bs[BKT][BN + 4];

    const float* Ab = A  + (size_t)blockIdx.z * strideA;
    const float* Bb = Bm + (size_t)blockIdx.z * strideB;
    float*       Cb = C  + (size_t)blockIdx.z * strideC;

    const int tid = threadIdx.x;
    const int tx = tid & 15;        // 0..15  (col group)
    const int ty = tid >> 4;        // 0..15  (row group)
    const int row0 = blockIdx.y * BM;
    const int col0 = blockIdx.x * BN;

    // A loader: each thread loads float4 along K
    const int aRow = tid >> 2;          // 0..63
    const int aK   = (tid & 3) * 4;     // 0,4,8,12
    // B loader (NN): float4 along N
    const int bK   = tid >> 4;          // 0..15
    const int bCol = (tid & 15) * 4;    // 0..60
    // B loader (NT): float4 along K
    const int bRowT = tid >> 2;         // 0..63 (n index)
    const int bKT_  = (tid & 3) * 4;    // 0,4,8,12

    float acc[4][4] = {};

    for (int k0 = 0; k0 < K; k0 += BKT) {
        // ---- load A tile (transposed into As[k][m]) ----
        float4 av = *reinterpret_cast<const float4*>(
            &Ab[(size_t)(row0 + aRow) * K + k0 + aK]);
        As[aK + 0][aRow] = av.x;
        As[aK + 1][aRow] = av.y;
        As[aK + 2][aRow] = av.z;
        As[aK + 3][aRow] = av.w;

        // ---- load B tile into Bs[k][n] ----
        if (!TRANSB) {
            float4 bv = *reinterpret_cast<const float4*>(
                &Bb[(size_t)(k0 + bK) * N + col0 + bCol]);
            Bs[bK][bCol + 0] = bv.x;
            Bs[bK][bCol + 1] = bv.y;
            Bs[bK][bCol + 2] = bv.z;
            Bs[bK][bCol + 3] = bv.w;
        } else {
            float4 bv = *reinterpret_cast<const float4*>(
                &Bb[(size_t)(col0 + bRowT) * K + k0 + bKT_]);
            Bs[bKT_ + 0][bRowT] = bv.x;
            Bs[bKT_ + 1][bRowT] = bv.y;
            Bs[bKT_ + 2][bRowT] = bv.z;
            Bs[bKT_ + 3][bRowT] = bv.w;
        }
        __syncthreads();

        // ---- compute ----
        #pragma unroll
        for (int kk = 0; kk < BKT; kk++) {
            float ra[4], rb[4];
            #pragma unroll
            for (int i = 0; i < 4; i++) ra[i] = As[kk][ty * 4 + i];
            #pragma unroll
            for (int j = 0; j < 4; j++) rb[j] = Bs[kk][tx * 4 + j];
            #pragma unroll
            for (int i = 0; i < 4; i++)
                #pragma unroll
                for (int j = 0; j < 4; j++)
                    acc[i][j] += ra[i] * rb[j];
        }
        __syncthreads();
    }

    // ---- store ----
    #pragma unroll
    for (int i = 0; i < 4; i++) {
        size_t r = (size_t)(row0 + ty * 4 + i) * N + col0 + tx * 4;
        #pragma unroll
        for (int j = 0; j < 4; j++)
            Cb[r + j] = alpha * acc[i][j];
    }
}

// ---------------- row softmax (in place) ----------------
// one block (256 threads) per row of length n
__global__ __launch_bounds__(256) void softmax_kernel(float* __restrict__ S, int n)
{
    float* row = S + (size_t)blockIdx.x * n;
    const int tid = threadIdx.x;
    __shared__ float red[256];

    float m = -INFINITY;
    for (int i = tid; i < n; i += 256) m = fmaxf(m, row[i]);
    red[tid] = m;
    __syncthreads();
    for (int s = 128; s > 0; s >>= 1) {
        if (tid < s) red[tid] = fmaxf(red[tid], red[tid + s]);
        __syncthreads();
    }
    m = red[0];
    __syncthreads();

    float sum = 0.f;
    for (int i = tid; i < n; i += 256) {
        float e = __expf(row[i] - m);
        row[i] = e;
        sum += e;
    }
    red[tid] = sum;
    __syncthreads();
    for (int s = 128; s > 0; s >>= 1) {
        if (tid < s) red[tid] += red[tid + s];
        __syncthreads();
    }
    const float inv = 1.0f / red[0];
    for (int i = tid; i < n; i += 256) row[i] *= inv;
}

// ---------------- launch ----------------
extern "C" void kernel_launch(void* const* d_in, const int* in_sizes, int n_in,
                              void* d_out, int out_size)
{
    const float* x   = (const float*)d_in[0];
    const float* W_q = (const float*)d_in[1];
    const float* W_k = (const float*)d_in[2];
    const float* W_v = (const float*)d_in[3];
    float* out = (float*)d_out;

    float* Q; cudaGetSymbolAddress((void**)&Q, g_Q);
    float* K; cudaGetSymbolAddress((void**)&K, g_K);
    float* V; cudaGetSymbolAddress((void**)&V, g_V);
    float* Sc; cudaGetSymbolAddress((void**)&Sc, g_S);

    const int M1 = BB * SS;       // 8192
    const float scale = 1.0f / sqrtf((float)UU);

    // 1) QKV projections: [8192,768] x [768,768]
    {
        dim3 grid(UU / BN, M1 / BM, 1);
        sgemm_kernel<false><<<grid, 256>>>(x, W_q, Q, M1, UU, DD, 0, 0, 0, 1.0f);
        sgemm_kernel<false><<<grid, 256>>>(x, W_k, K, M1, UU, DD, 0, 0, 0, 1.0f);
        sgemm_kernel<false><<<grid, 256>>>(x, W_v, V, M1, UU, DD, 0, 0, 0, 1.0f);
    }

    // 2) scores = scale * Q Kt : per batch [2048,2048,768], NT
    {
        dim3 grid(SS / BN, SS / BM, BB);
        sgemm_kernel<true><<<grid, 256>>>(
            Q, K, Sc, SS, SS, UU,
            (size_t)SS * UU, (size_t)SS * UU, (size_t)SS * SS, scale);
    }

    // 3) softmax rows
    {
        softmax_kernel<<<BB * SS, 256>>>(Sc, SS);
    }

    // 4) out = attn V : per batch [2048,768,2048], NN
    {
        dim3 grid(UU / BN, SS / BM, BB);
        sgemm_kernel<false><<<grid, 256>>>(
            Sc, V, out, SS, UU, SS,
            (size_t)SS * SS, (size_t)SS * UU, (size_t)SS * UU, 1.0f);
    }
}

// round 4
// speedup vs baseline: 1.2371x; 1.2371x over previous
#include <cuda_runtime.h>
#include <math.h>

// Problem dims (fixed per reference)
#define BB 4
#define SS 2048
#define DD 768
#define UU 768

// ---------------- scratch (no allocations allowed) ----------------
__device__ float g_Q[(size_t)BB * SS * UU];
__device__ float g_K[(size_t)BB * SS * UU];
__device__ float g_V[(size_t)BB * SS * UU];
__device__ float g_S[(size_t)BB * SS * SS];

// ---------------- tiled SGEMM ----------------
// C[M,N] = alpha * A[M,K] * op(B)   op(B)=B[K,N] (NN) or B[N,K]^T (NT)
// 128x128 block tile, BK=16, 256 threads, 8x8 per-thread micro-tile
// (split 4+4 fragments for conflict-free LDS.128), double-buffered smem.
#define BM 128
#define BN 128
#define BKT 16

template <bool TRANSB>
__global__ __launch_bounds__(256) void sgemm_kernel(
    const float* __restrict__ A, const float* __restrict__ Bm,
    float* __restrict__ C,
    int M, int N, int K,
    size_t strideA, size_t strideB, size_t strideC,
    float alpha)
{
    __shared__ float As[2][BKT][BM + 4];
    __shared__ float Bs[2][BKT][BN + 4];

    const float* Ab = A  + (size_t)blockIdx.z * strideA;
    const float* Bb = Bm + (size_t)blockIdx.z * strideB;
    float*       Cb = C  + (size_t)blockIdx.z * strideC;

    const int tid  = threadIdx.x;
    const int lane = tid & 31;
    const int warp = tid >> 5;
    const int wr = warp & 3;    // 4 warps along M -> warp tile 32 rows
    const int wc = warp >> 2;   // 2 warps along N -> warp tile 64 cols
    const int tm = lane >> 3;   // 0..3
    const int tn = lane & 7;    // 0..7

    const int row0 = blockIdx.y * BM;
    const int col0 = blockIdx.x * BN;

    // fragment offsets inside block tile
    const int aOff = wr * 32 + tm * 4;   // rows aOff..+3 and aOff+16..+19
    const int bOff = wc * 64 + tn * 4;   // cols bOff..+3 and bOff+32..+35

    // ---- global loaders ----
    // A tile: 128 rows x 16 k. thread: row=tid>>1, k-offset=(tid&1)*8
    const int aRow = tid >> 1;
    const int aK   = (tid & 1) * 8;
    // B NN tile: 16 k x 128 n. thread: k=tid>>4, n=(tid&15)*4 (+64)
    const int bK  = tid >> 4;
    const int bN  = (tid & 15) * 4;
    // B NT tile: 128 n-rows x 16 k. thread: n=tid>>1, k-offset=(tid&1)*8
    const int bRowT = tid >> 1;
    const int bKT_  = (tid & 1) * 8;

    float acc[8][8] = {};

    const int nIter = K / BKT;

    // ---- preload tile 0 into buffer 0 ----
    {
        float4 a0 = *reinterpret_cast<const float4*>(&Ab[(size_t)(row0 + aRow) * K + aK]);
        float4 a1 = *reinterpret_cast<const float4*>(&Ab[(size_t)(row0 + aRow) * K + aK + 4]);
        As[0][aK + 0][aRow] = a0.x; As[0][aK + 1][aRow] = a0.y;
        As[0][aK + 2][aRow] = a0.z; As[0][aK + 3][aRow] = a0.w;
        As[0][aK + 4][aRow] = a1.x; As[0][aK + 5][aRow] = a1.y;
        As[0][aK + 6][aRow] = a1.z; As[0][aK + 7][aRow] = a1.w;
        if (!TRANSB) {
            float4 b0 = *reinterpret_cast<const float4*>(&Bb[(size_t)bK * N + col0 + bN]);
            float4 b1 = *reinterpret_cast<const float4*>(&Bb[(size_t)bK * N + col0 + bN + 64]);
            *reinterpret_cast<float4*>(&Bs[0][bK][bN])      = b0;
            *reinterpret_cast<float4*>(&Bs[0][bK][bN + 64]) = b1;
        } else {
            float4 b0 = *reinterpret_cast<const float4*>(&Bb[(size_t)(col0 + bRowT) * K + bKT_]);
            float4 b1 = *reinterpret_cast<const float4*>(&Bb[(size_t)(col0 + bRowT) * K + bKT_ + 4]);
            Bs[0][bKT_ + 0][bRowT] = b0.x; Bs[0][bKT_ + 1][bRowT] = b0.y;
            Bs[0][bKT_ + 2][bRowT] = b0.z; Bs[0][bKT_ + 3][bRowT] = b0.w;
            Bs[0][bKT_ + 4][bRowT] = b1.x; Bs[0][bKT_ + 5][bRowT] = b1.y;
            Bs[0][bKT_ + 6][bRowT] = b1.z; Bs[0][bKT_ + 7][bRowT] = b1.w;
        }
    }
    __syncthreads();

    float4 pa0, pa1, pb0, pb1;

    for (int it = 0; it < nIter; ++it) {
        const int cur = it & 1;
        const int k0n = (it + 1) * BKT;
        const bool more = (it + 1 < nIter);

        // prefetch next tile into registers (hide global latency behind compute)
        if (more) {
            pa0 = *reinterpret_cast<const float4*>(&Ab[(size_t)(row0 + aRow) * K + k0n + aK]);
            pa1 = *reinterpret_cast<const float4*>(&Ab[(size_t)(row0 + aRow) * K + k0n + aK + 4]);
            if (!TRANSB) {
                pb0 = *reinterpret_cast<const float4*>(&Bb[(size_t)(k0n + bK) * N + col0 + bN]);
                pb1 = *reinterpret_cast<const float4*>(&Bb[(size_t)(k0n + bK) * N + col0 + bN + 64]);
            } else {
                pb0 = *reinterpret_cast<const float4*>(&Bb[(size_t)(col0 + bRowT) * K + k0n + bKT_]);
                pb1 = *reinterpret_cast<const float4*>(&Bb[(size_t)(col0 + bRowT) * K + k0n + bKT_ + 4]);
            }
        }

        // ---- compute on buffer `cur` ----
        #pragma unroll
        for (int kk = 0; kk < BKT; ++kk) {
            float4 a0 = *reinterpret_cast<const float4*>(&As[cur][kk][aOff]);
            float4 a1 = *reinterpret_cast<const float4*>(&As[cur][kk][aOff + 16]);
            float4 b0 = *reinterpret_cast<const float4*>(&Bs[cur][kk][bOff]);
            float4 b1 = *reinterpret_cast<const float4*>(&Bs[cur][kk][bOff + 32]);
            float ra[8] = {a0.x, a0.y, a0.z, a0.w, a1.x, a1.y, a1.z, a1.w};
            float rb[8] = {b0.x, b0.y, b0.z, b0.w, b1.x, b1.y, b1.z, b1.w};
            #pragma unroll
            for (int i = 0; i < 8; ++i)
                #pragma unroll
                for (int j = 0; j < 8; ++j)
                    acc[i][j] += ra[i] * rb[j];
        }

        // ---- commit prefetch into the other buffer ----
        if (more) {
            const int nxt = cur ^ 1;
            As[nxt][aK + 0][aRow] = pa0.x; As[nxt][aK + 1][aRow] = pa0.y;
            As[nxt][aK + 2][aRow] = pa0.z; As[nxt][aK + 3][aRow] = pa0.w;
            As[nxt][aK + 4][aRow] = pa1.x; As[nxt][aK + 5][aRow] = pa1.y;
            As[nxt][aK + 6][aRow] = pa1.z; As[nxt][aK + 7][aRow] = pa1.w;
            if (!TRANSB) {
                *reinterpret_cast<float4*>(&Bs[nxt][bK][bN])      = pb0;
                *reinterpret_cast<float4*>(&Bs[nxt][bK][bN + 64]) = pb1;
            } else {
                Bs[nxt][bKT_ + 0][bRowT] = pb0.x; Bs[nxt][bKT_ + 1][bRowT] = pb0.y;
                Bs[nxt][bKT_ + 2][bRowT] = pb0.z; Bs[nxt][bKT_ + 3][bRowT] = pb0.w;
                Bs[nxt][bKT_ + 4][bRowT] = pb1.x; Bs[nxt][bKT_ + 5][bRowT] = pb1.y;
                Bs[nxt][bKT_ + 6][bRowT] = pb1.z; Bs[nxt][bKT_ + 7][bRowT] = pb1.w;
            }
            __syncthreads();
        }
    }

    // ---- store 8x8 (two float4 per row) ----
    #pragma unroll
    for (int i = 0; i < 8; ++i) {
        const int r = row0 + aOff + ((i < 4) ? i : (12 + i));  // +0..3, +16..19
        float4 v0, v1;
        v0.x = alpha * acc[i][0]; v0.y = alpha * acc[i][1];
        v0.z = alpha * acc[i][2]; v0.w = alpha * acc[i][3];
        v1.x = alpha * acc[i][4]; v1.y = alpha * acc[i][5];
        v1.z = alpha * acc[i][6]; v1.w = alpha * acc[i][7];
        *reinterpret_cast<float4*>(&Cb[(size_t)r * N + col0 + bOff])      = v0;
        *reinterpret_cast<float4*>(&Cb[(size_t)r * N + col0 + bOff + 32]) = v1;
    }
}

// ---------------- row softmax (in place, single pass over gmem) ----------------
// one block (256 threads) per row of 2048; each thread keeps 8 values in regs
__global__ __launch_bounds__(256) void softmax_kernel(float* __restrict__ S)
{
    float* row = S + (size_t)blockIdx.x * SS;
    const int tid = threadIdx.x;
    __shared__ float red[32];

    float4 v0 = *reinterpret_cast<const float4*>(&row[tid * 8]);
    float4 v1 = *reinterpret_cast<const float4*>(&row[tid * 8 + 4]);

    // --- max ---
    float m = fmaxf(fmaxf(fmaxf(v0.x, v0.y), fmaxf(v0.z, v0.w)),
                    fmaxf(fmaxf(v1.x, v1.y), fmaxf(v1.z, v1.w)));
    #pragma unroll
    for (int s = 16; s > 0; s >>= 1)
        m = fmaxf(m, __shfl_xor_sync(0xffffffff, m, s));
    if ((tid & 31) == 0) red[tid >> 5] = m;
    __syncthreads();
    {
        float t = red[tid & 7];
        #pragma unroll
        for (int s = 4; s > 0; s >>= 1)
            t = fmaxf(t, __shfl_xor_sync(0xffffffff, t, s));
        m = t;
    }

    // --- exp + sum ---
    v0.x = __expf(v0.x - m); v0.y = __expf(v0.y - m);
    v0.z = __expf(v0.z - m); v0.w = __expf(v0.w - m);
    v1.x = __expf(v1.x - m); v1.y = __expf(v1.y - m);
    v1.z = __expf(v1.z - m); v1.w = __expf(v1.w - m);
    float sum = v0.x + v0.y + v0.z + v0.w + v1.x + v1.y + v1.z + v1.w;
    #pragma unroll
    for (int s = 16; s > 0; s >>= 1)
        sum += __shfl_xor_sync(0xffffffff, sum, s);
    __syncthreads();
    if ((tid & 31) == 0) red[tid >> 5] = sum;
    __syncthreads();
    {
        float t = red[tid & 7];
        #pragma unroll
        for (int s = 4; s > 0; s >>= 1)
            t += __shfl_xor_sync(0xffffffff, t, s);
        sum = t;
    }

    const float inv = 1.0f / sum;
    v0.x *= inv; v0.y *= inv; v0.z *= inv; v0.w *= inv;
    v1.x *= inv; v1.y *= inv; v1.z *= inv; v1.w *= inv;
    *reinterpret_cast<float4*>(&row[tid * 8])     = v0;
    *reinterpret_cast<float4*>(&row[tid * 8 + 4]) = v1;
}

// ---------------- launch ----------------
extern "C" void kernel_launch(void* const* d_in, const int* in_sizes, int n_in,
                              void* d_out, int out_size)
{
    const float* x   = (const float*)d_in[0];
    const float* W_q = (const float*)d_in[1];
    const float* W_k = (const float*)d_in[2];
    const float* W_v = (const float*)d_in[3];
    float* out = (float*)d_out;

    float* Q; cudaGetSymbolAddress((void**)&Q, g_Q);
    float* K; cudaGetSymbolAddress((void**)&K, g_K);
    float* V; cudaGetSymbolAddress((void**)&V, g_V);
    float* Sc; cudaGetSymbolAddress((void**)&Sc, g_S);

    const int M1 = BB * SS;       // 8192
    const float scale = 1.0f / sqrtf((float)UU);

    // 1) QKV projections: [8192,768] x [768,768]
    {
        dim3 grid(UU / BN, M1 / BM, 1);
        sgemm_kernel<false><<<grid, 256>>>(x, W_q, Q, M1, UU, DD, 0, 0, 0, 1.0f);
        sgemm_kernel<false><<<grid, 256>>>(x, W_k, K, M1, UU, DD, 0, 0, 0, 1.0f);
        sgemm_kernel<false><<<grid, 256>>>(x, W_v, V, M1, UU, DD, 0, 0, 0, 1.0f);
    }

    // 2) scores = scale * Q Kt : per batch [2048,2048,768], NT
    {
        dim3 grid(SS / BN, SS / BM, BB);
        sgemm_kernel<true><<<grid, 256>>>(
            Q, K, Sc, SS, SS, UU,
            (size_t)SS * UU, (size_t)SS * UU, (size_t)SS * SS, scale);
    }

    // 3) softmax rows
    {
        softmax_kernel<<<BB * SS, 256>>>(Sc);
    }

    // 4) out = attn V : per batch [2048,768,2048], NN
    {
        dim3 grid(UU / BN, SS / BM, BB);
        sgemm_kernel<false><<<grid, 256>>>(
            Sc, V, out, SS, UU, SS,
            (size_t)SS * SS, (size_t)SS * UU, (size_t)SS * UU, 1.0f);
    }
}

// round 6
// speedup vs baseline: 2.0162x; 1.6298x over previous
#include <cuda_runtime.h>
#include <cuda_bf16.h>
#include <math.h>

// Problem dims (fixed per reference)
#define BB 4
#define SS 2048
#define DD 768
#define UU 768

// ---------------- scratch (no allocations allowed) ----------------
__device__ float g_Q[(size_t)BB * SS * UU];
__device__ float g_K[(size_t)BB * SS * UU];
__device__ float g_V[(size_t)BB * SS * UU];
__device__ float g_Vt[(size_t)BB * SS * UU];
__device__ float g_Wt[(size_t)3 * DD * UU];
__device__ float g_S[(size_t)BB * SS * SS];

// =============================================================
// bf16x2 split-precision tensor-core GEMM (NT form)
// C[M,N] = alpha * A[M,K] * B[N,K]^T   (A,B row-major, K contiguous)
// a = a_hi + a_lo (bf16 each); D += ah*bh + ah*bl + al*bh  (fp32 accum)
// 128x128 block tile, BK=16 (one m16n8k16 step), 8 warps (2x4),
// warp tile 64x32 (4x4 atoms), double-buffered smem + reg prefetch.
// =============================================================
#define BM 128
#define BN 128
#define BK 16
#define AP 40   // smem row pitch in bf16 elems: hi k0..15, lo k16..31, pad 8
                // word-pitch 20 -> frag LDS conflict-free (8 rows x 4 kp cover 32 banks)

__device__ __forceinline__ void cvt_pack8(float4 v0, float4 v1, uint4& hi, uint4& lo)
{
    float f[8] = {v0.x, v0.y, v0.z, v0.w, v1.x, v1.y, v1.z, v1.w};
    unsigned h[8], l[8];
#pragma unroll
    for (int i = 0; i < 8; i++) {
        __nv_bfloat16 bh = __float2bfloat16_rn(f[i]);
        float r = f[i] - __bfloat162float(bh);
        __nv_bfloat16 bl = __float2bfloat16_rn(r);
        h[i] = (unsigned)__bfloat16_as_ushort(bh);
        l[i] = (unsigned)__bfloat16_as_ushort(bl);
    }
    hi = make_uint4(h[0] | (h[1] << 16), h[2] | (h[3] << 16),
                    h[4] | (h[5] << 16), h[6] | (h[7] << 16));
    lo = make_uint4(l[0] | (l[1] << 16), l[2] | (l[3] << 16),
                    l[4] | (l[5] << 16), l[6] | (l[7] << 16));
}

__device__ __forceinline__ void mma_bf16(float* c, const unsigned* a, const unsigned* b)
{
    asm volatile(
        "mma.sync.aligned.m16n8k16.row.col.f32.bf16.bf16.f32 "
        "{%0,%1,%2,%3}, {%4,%5,%6,%7}, {%8,%9}, {%0,%1,%2,%3};\n"
        : "+f"(c[0]), "+f"(c[1]), "+f"(c[2]), "+f"(c[3])
        : "r"(a[0]), "r"(a[1]), "r"(a[2]), "r"(a[3]), "r"(b[0]), "r"(b[1]));
}

__global__ __launch_bounds__(256) void gemm_bf16x2(
    const float* __restrict__ A, const float* __restrict__ B, float* __restrict__ C,
    int M, int N, int K,
    size_t sA, size_t sB, size_t sC, float alpha)
{
    __shared__ __align__(16) unsigned short As[2][BM][AP];
    __shared__ __align__(16) unsigned short Bs[2][BN][AP];

    const float* Ab = A + (size_t)blockIdx.z * sA;
    const float* Bb = B + (size_t)blockIdx.z * sB;
    float*       Cb = C + (size_t)blockIdx.z * sC;

    const int tid  = threadIdx.x;
    const int lane = tid & 31;
    const int warp = tid >> 5;
    const int warpM = (warp >> 2) * 64;   // 2 warps along M
    const int warpN = (warp & 3) * 32;    // 4 warps along N
    const int g  = lane >> 2;             // 0..7
    const int kp = (lane & 3) * 2;        // 0,2,4,6

    const int row0 = blockIdx.y * BM;
    const int col0 = blockIdx.x * BN;

    // staging loaders: each thread 8 floats of one row
    const int ldRow = tid >> 1;           // 0..127
    const int ldK   = (tid & 1) * 8;      // 0 or 8
    const float* aPtr = Ab + (size_t)(row0 + ldRow) * K + ldK;
    const float* bPtr = Bb + (size_t)(col0 + ldRow) * K + ldK;

    // ---- preload tile 0 ----
    {
        uint4 hi, lo;
        cvt_pack8(*(const float4*)aPtr, *(const float4*)(aPtr + 4), hi, lo);
        *(uint4*)&As[0][ldRow][ldK]      = hi;
        *(uint4*)&As[0][ldRow][ldK + 16] = lo;
        cvt_pack8(*(const float4*)bPtr, *(const float4*)(bPtr + 4), hi, lo);
        *(uint4*)&Bs[0][ldRow][ldK]      = hi;
        *(uint4*)&Bs[0][ldRow][ldK + 16] = lo;
    }
    __syncthreads();

    float acc[4][4][4] = {};
    const int nIter = K / BK;
    float4 pa0, pa1, pb0, pb1;

    for (int it = 0; it < nIter; ++it) {
        const int cur = it & 1;
        const bool more = (it + 1 < nIter);

        if (more) {
            const float* ap = aPtr + (it + 1) * BK;
            const float* bp = bPtr + (it + 1) * BK;
            pa0 = *(const float4*)ap; pa1 = *(const float4*)(ap + 4);
            pb0 = *(const float4*)bp; pb1 = *(const float4*)(bp + 4);
        }

        // ---- B fragments (hi+lo) for all 4 n-atoms ----
        unsigned bh[4][2], bl[4][2];
#pragma unroll
        for (int ni = 0; ni < 4; ni++) {
            const unsigned short* bp = &Bs[cur][warpN + ni * 8 + g][0];
            bh[ni][0] = *(const unsigned*)(bp + kp);
            bh[ni][1] = *(const unsigned*)(bp + kp + 8);
            bl[ni][0] = *(const unsigned*)(bp + kp + 16);
            bl[ni][1] = *(const unsigned*)(bp + kp + 24);
        }

        // ---- per m-atom: load A frags, 3 mmas per (mi,ni) ----
#pragma unroll
        for (int mi = 0; mi < 4; mi++) {
            const unsigned short* a0p = &As[cur][warpM + mi * 16 + g][0];
            const unsigned short* a1p = &As[cur][warpM + mi * 16 + g + 8][0];
            unsigned ah[4] = { *(const unsigned*)(a0p + kp),      *(const unsigned*)(a1p + kp),
                               *(const unsigned*)(a0p + kp + 8),  *(const unsigned*)(a1p + kp + 8) };
            unsigned al[4] = { *(const unsigned*)(a0p + kp + 16), *(const unsigned*)(a1p + kp + 16),
                               *(const unsigned*)(a0p + kp + 24), *(const unsigned*)(a1p + kp + 24) };
#pragma unroll
            for (int ni = 0; ni < 4; ni++) {
                mma_bf16(acc[mi][ni], ah, bh[ni]);   // hi*hi
                mma_bf16(acc[mi][ni], ah, bl[ni]);   // hi*lo
                mma_bf16(acc[mi][ni], al, bh[ni]);   // lo*hi
            }
        }

        if (more) {
            const int nxt = cur ^ 1;
            uint4 hi, lo;
            cvt_pack8(pa0, pa1, hi, lo);
            *(uint4*)&As[nxt][ldRow][ldK]      = hi;
            *(uint4*)&As[nxt][ldRow][ldK + 16] = lo;
            cvt_pack8(pb0, pb1, hi, lo);
            *(uint4*)&Bs[nxt][ldRow][ldK]      = hi;
            *(uint4*)&Bs[nxt][ldRow][ldK + 16] = lo;
            __syncthreads();
        }
    }

    // ---- epilogue: float2 stores (c-frag pairs) ----
#pragma unroll
    for (int mi = 0; mi < 4; mi++) {
#pragma unroll
        for (int h = 0; h < 2; h++) {
            const int row = row0 + warpM + mi * 16 + g + h * 8;
#pragma unroll
            for (int ni = 0; ni < 4; ni++) {
                const int col = col0 + warpN + ni * 8 + (lane & 3) * 2;
                float2 v = make_float2(alpha * acc[mi][ni][h * 2],
                                       alpha * acc[mi][ni][h * 2 + 1]);
                *(float2*)&Cb[(size_t)row * N + col] = v;
            }
        }
    }
}

// ---------------- tiled transpose: out[c][r] = in[r][c], batched via z ----------------
__global__ __launch_bounds__(256) void transpose_kernel(
    const float* __restrict__ in, float* __restrict__ out, int R, int C)
{
    __shared__ float t[32][33];
    in  += (size_t)blockIdx.z * R * C;
    out += (size_t)blockIdx.z * R * C;
    const int c0 = blockIdx.x * 32, r0 = blockIdx.y * 32;
    const int tx = threadIdx.x & 31, ty = threadIdx.x >> 5;  // 32x8
#pragma unroll
    for (int j = 0; j < 32; j += 8)
        t[ty + j][tx] = in[(size_t)(r0 + ty + j) * C + c0 + tx];
    __syncthreads();
#pragma unroll
    for (int j = 0; j < 32; j += 8)
        out[(size_t)(c0 + ty + j) * R + r0 + tx] = t[tx][ty + j];
}

// ---------------- row softmax (in place, single pass over gmem) ----------------
__global__ __launch_bounds__(256) void softmax_kernel(float* __restrict__ S)
{
    float* row = S + (size_t)blockIdx.x * SS;
    const int tid = threadIdx.x;
    __shared__ float red[32];

    float4 v0 = *reinterpret_cast<const float4*>(&row[tid * 8]);
    float4 v1 = *reinterpret_cast<const float4*>(&row[tid * 8 + 4]);

    float m = fmaxf(fmaxf(fmaxf(v0.x, v0.y), fmaxf(v0.z, v0.w)),
                    fmaxf(fmaxf(v1.x, v1.y), fmaxf(v1.z, v1.w)));
#pragma unroll
    for (int s = 16; s > 0; s >>= 1)
        m = fmaxf(m, __shfl_xor_sync(0xffffffff, m, s));
    if ((tid & 31) == 0) red[tid >> 5] = m;
    __syncthreads();
    {
        float t = red[tid & 7];
#pragma unroll
        for (int s = 4; s > 0; s >>= 1)
            t = fmaxf(t, __shfl_xor_sync(0xffffffff, t, s));
        m = t;
    }

    v0.x = __expf(v0.x - m); v0.y = __expf(v0.y - m);
    v0.z = __expf(v0.z - m); v0.w = __expf(v0.w - m);
    v1.x = __expf(v1.x - m); v1.y = __expf(v1.y - m);
    v1.z = __expf(v1.z - m); v1.w = __expf(v1.w - m);
    float sum = v0.x + v0.y + v0.z + v0.w + v1.x + v1.y + v1.z + v1.w;
#pragma unroll
    for (int s = 16; s > 0; s >>= 1)
        sum += __shfl_xor_sync(0xffffffff, sum, s);
    __syncthreads();
    if ((tid & 31) == 0) red[tid >> 5] = sum;
    __syncthreads();
    {
        float t = red[tid & 7];
#pragma unroll
        for (int s = 4; s > 0; s >>= 1)
            t += __shfl_xor_sync(0xffffffff, t, s);
        sum = t;
    }

    const float inv = 1.0f / sum;
    v0.x *= inv; v0.y *= inv; v0.z *= inv; v0.w *= inv;
    v1.x *= inv; v1.y *= inv; v1.z *= inv; v1.w *= inv;
    *reinterpret_cast<float4*>(&row[tid * 8])     = v0;
    *reinterpret_cast<float4*>(&row[tid * 8 + 4]) = v1;
}

// ---------------- launch ----------------
extern "C" void kernel_launch(void* const* d_in, const int* in_sizes, int n_in,
                              void* d_out, int out_size)
{
    const float* x   = (const float*)d_in[0];
    const float* W_q = (const float*)d_in[1];
    const float* W_k = (const float*)d_in[2];
    const float* W_v = (const float*)d_in[3];
    float* out = (float*)d_out;

    float* Q;  cudaGetSymbolAddress((void**)&Q,  g_Q);
    float* K;  cudaGetSymbolAddress((void**)&K,  g_K);
    float* V;  cudaGetSymbolAddress((void**)&V,  g_V);
    float* Vt; cudaGetSymbolAddress((void**)&Vt, g_Vt);
    float* Wt; cudaGetSymbolAddress((void**)&Wt, g_Wt);
    float* Sc; cudaGetSymbolAddress((void**)&Sc, g_S);

    const int M1 = BB * SS;  // 8192
    const float scale = 1.0f / sqrtf((float)UU);

    // 0) transpose weights: Wt_i[u][d] = W_i[d][u]
    {
        dim3 grid(UU / 32, DD / 32, 1);
        dim3 blk(256);
        transpose_kernel<<<grid, blk>>>(W_q, Wt + 0 * (size_t)DD * UU, DD, UU);
        transpose_kernel<<<grid, blk>>>(W_k, Wt + 1 * (size_t)DD * UU, DD, UU);
        transpose_kernel<<<grid, blk>>>(W_v, Wt + 2 * (size_t)DD * UU, DD, UU);
    }

    // 1) projections: [8192,768] x Wt[768 n][768 k]^T
    {
        dim3 grid(UU / BN, M1 / BM, 1);
        gemm_bf16x2<<<grid, 256>>>(x, Wt + 0 * (size_t)DD * UU, Q, M1, UU, DD, 0, 0, 0, 1.0f);
        gemm_bf16x2<<<grid, 256>>>(x, Wt + 1 * (size_t)DD * UU, K, M1, UU, DD, 0, 0, 0, 1.0f);
        gemm_bf16x2<<<grid, 256>>>(x, Wt + 2 * (size_t)DD * UU, V, M1, UU, DD, 0, 0, 0, 1.0f);
    }

    // 2) transpose V per batch: Vt[b][u][s]
    {
        dim3 grid(UU / 32, SS / 32, BB);
        transpose_kernel<<<grid, 256>>>(V, Vt, SS, UU);
    }

    // 3) scores = scale * Q K^T (B = K, already [n=s2][k=u])
    {
        dim3 grid(SS / BN, SS / BM, BB);
        gemm_bf16x2<<<grid, 256>>>(Q, K, Sc, SS, SS, UU,
                                   (size_t)SS * UU, (size_t)SS * UU, (size_t)SS * SS, scale);
    }

    // 4) softmax rows
    softmax_kernel<<<BB * SS, 256>>>(Sc);

    // 5) out = attn * V  (B = Vt[u][s] -> NT form)
    {
        dim3 grid(UU / BN, SS / BM, BB);
        gemm_bf16x2<<<grid, 256>>>(Sc, Vt, out, SS, UU, SS,
                                   (size_t)SS * SS, (size_t)SS * UU, (size_t)SS * UU, 1.0f);
    }
}

// round 9
// speedup vs baseline: 2.2057x; 1.0940x over previous
#include <cuda_runtime.h>
#include <cuda_bf16.h>
#include <math.h>

// Problem dims (fixed per reference)
#define BB 4
#define SS 2048
#define DD 768
#define UU 768

typedef unsigned short u16;
typedef unsigned int   u32;

// ---------------- scratch (no allocations allowed) ----------------
__device__ u16   g_xh [(size_t)BB*SS*DD];
__device__ u16   g_xl [(size_t)BB*SS*DD];
__device__ u16   g_Wth[(size_t)3*DD*UU];
__device__ u16   g_Wtl[(size_t)3*DD*UU];
__device__ u16   g_Qh [(size_t)BB*SS*UU];
__device__ u16   g_Ql [(size_t)BB*SS*UU];
__device__ u16   g_Kh [(size_t)BB*SS*UU];
__device__ u16   g_Kl [(size_t)BB*SS*UU];
__device__ float g_V  [(size_t)BB*SS*UU];
__device__ u16   g_Vth[(size_t)BB*SS*UU];
__device__ u16   g_Vtl[(size_t)BB*SS*UU];
__device__ float g_S  [(size_t)BB*SS*SS];
__device__ u16   g_Ph [(size_t)BB*SS*SS];
__device__ u16   g_Pl [(size_t)BB*SS*SS];

// ---------------- helpers ----------------
__device__ __forceinline__ u32 s2u(const void* p) {
    u32 a;
    asm("{ .reg .u64 t; cvta.to.shared.u64 t, %1; cvt.u32.u64 %0, t; }"
        : "=r"(a) : "l"(p));
    return a;
}

__device__ __forceinline__ void cpasync16(u32 dst, const void* src) {
    asm volatile("cp.async.cg.shared.global [%0], [%1], 16;"
                 :: "r"(dst), "l"(src) : "memory");
}
__device__ __forceinline__ void cp_commit() {
    asm volatile("cp.async.commit_group;" ::: "memory");
}
template <int N>
__device__ __forceinline__ void cp_wait() {
    asm volatile("cp.async.wait_group %0;" :: "n"(N) : "memory");
}

__device__ __forceinline__ void ldm_x4(u32 addr, u32& r0, u32& r1, u32& r2, u32& r3) {
    asm volatile("ldmatrix.sync.aligned.m8n8.x4.shared.b16 {%0,%1,%2,%3}, [%4];"
                 : "=r"(r0), "=r"(r1), "=r"(r2), "=r"(r3) : "r"(addr));
}

__device__ __forceinline__ void mma_bf16(float* c, const u32* a, const u32* b) {
    asm volatile(
        "mma.sync.aligned.m16n8k16.row.col.f32.bf16.bf16.f32 "
        "{%0,%1,%2,%3}, {%4,%5,%6,%7}, {%8,%9}, {%0,%1,%2,%3};\n"
        : "+f"(c[0]), "+f"(c[1]), "+f"(c[2]), "+f"(c[3])
        : "r"(a[0]), "r"(a[1]), "r"(a[2]), "r"(a[3]), "r"(b[0]), "r"(b[1]));
}

__device__ __forceinline__ void split2(float a, float b, u32& h, u32& l) {
    __nv_bfloat16 ah = __float2bfloat16_rn(a), bh = __float2bfloat16_rn(b);
    __nv_bfloat16 al = __float2bfloat16_rn(a - __bfloat162float(ah));
    __nv_bfloat16 bl = __float2bfloat16_rn(b - __bfloat162float(bh));
    h = (u32)__bfloat16_as_ushort(ah) | ((u32)__bfloat16_as_ushort(bh) << 16);
    l = (u32)__bfloat16_as_ushort(al) | ((u32)__bfloat16_as_ushort(bl) << 16);
}

// =============================================================
// mma.sync bf16x2 GEMM (NT): C[M,N] = alpha * A[M,K] * B[N,K]^T
// Split hi/lo bf16 inputs. 128x128 block tile, K-chunk 64 (SW128
// 128B rows), cp.async double buffer, ldmatrix.x4 fragments,
// 8 warps (2x4), warp tile 64x32, 3 mma terms per k16 step.
// =============================================================
#define KC 64
#define TILEB 16384           // 128 rows * 128 B
#define BUFB  (4 * TILEB)     // AH, AL, BH, BL
#define SMEM_BYTES (2 * BUFB) // 131072

// swizzled ldmatrix address: row*128B, 16B-chunk = (ks*2 | khalf) ^ (row&7)
__device__ __forceinline__ u32 lm_addr(u32 tile, int row, int ks, int khalf) {
    return tile + (u32)row * 128u + (u32)((((ks << 1) | khalf) ^ (row & 7)) << 4);
}

template <bool SPLIT_OUT>
__global__ __launch_bounds__(256, 1) void gemm_mma(
    const u16* __restrict__ Ah, const u16* __restrict__ Al,
    const u16* __restrict__ Bh, const u16* __restrict__ Bl,
    float* __restrict__ Cf, u16* __restrict__ Ch, u16* __restrict__ Cl,
    int M, int N, int K,
    size_t sA, size_t sB, size_t sC, float alpha)
{
    extern __shared__ __align__(1024) char smem[];
    const u32 sb = s2u(smem);
    const int tid  = threadIdx.x;
    const int lane = tid & 31;
    const int warp = tid >> 5;

    Ah += (size_t)blockIdx.z * sA;  Al += (size_t)blockIdx.z * sA;
    Bh += (size_t)blockIdx.z * sB;  Bl += (size_t)blockIdx.z * sB;

    const int row0 = blockIdx.y * 128;
    const int col0 = blockIdx.x * 128;

    const int warpM = (warp >> 2) * 64;   // 2 warps along M
    const int warpN = (warp & 3) * 32;    // 4 warps along N
    const int lrow  = lane & 15;
    const int khalf = lane >> 4;

    // ---- staging geometry: 2 threads/row, 64B each (4x 16B) ----
    const int r    = tid >> 1;
    const int half = tid & 1;
    u32 swo[4];
#pragma unroll
    for (int i = 0; i < 4; i++) {
        u32 off = (u32)r * 128u + (u32)half * 64u + (u32)i * 16u;
        swo[i] = off ^ ((off >> 3) & 0x70);
    }
    const u16* gAh = Ah + (size_t)(row0 + r) * K + half * 32;
    const u16* gAl = Al + (size_t)(row0 + r) * K + half * 32;
    const u16* gBh = Bh + (size_t)(col0 + r) * K + half * 32;
    const u16* gBl = Bl + (size_t)(col0 + r) * K + half * 32;

    const int nC = K / KC;

    // issue all 16 cp.async for chunk c into buffer buf
    auto load_chunk = [&](int c, int buf) {
        const u32 tb = sb + (u32)buf * BUFB;
        const int ko = c * KC;
#pragma unroll
        for (int i = 0; i < 4; i++) {
            cpasync16(tb + 0 * TILEB + swo[i], gAh + ko + i * 8);
            cpasync16(tb + 1 * TILEB + swo[i], gAl + ko + i * 8);
            cpasync16(tb + 2 * TILEB + swo[i], gBh + ko + i * 8);
            cpasync16(tb + 3 * TILEB + swo[i], gBl + ko + i * 8);
        }
    };

    float acc[4][4][4] = {};

    load_chunk(0, 0);
    cp_commit();

    for (int c = 0; c < nC; c++) {
        const int buf = c & 1;
        if (c + 1 < nC) {
            load_chunk(c + 1, buf ^ 1);
            cp_commit();
            cp_wait<1>();
        } else {
            cp_wait<0>();
        }
        __syncthreads();

        const u32 tAh = sb + (u32)buf * BUFB;
        const u32 tAl = tAh + TILEB;
        const u32 tBh = tAh + 2 * TILEB;
        const u32 tBl = tAh + 3 * TILEB;

#pragma unroll
        for (int ks = 0; ks < 4; ks++) {
            // B fragments: 2 n-halves, hi+lo
            u32 bh[4][2], bl[4][2];
#pragma unroll
            for (int h = 0; h < 2; h++) {
                const int rowB = warpN + h * 16 + lrow;
                u32 r0, r1, r2, r3;
                ldm_x4(lm_addr(tBh, rowB, ks, khalf), r0, r1, r2, r3);
                bh[2*h][0] = r0; bh[2*h+1][0] = r1;
                bh[2*h][1] = r2; bh[2*h+1][1] = r3;
                ldm_x4(lm_addr(tBl, rowB, ks, khalf), r0, r1, r2, r3);
                bl[2*h][0] = r0; bl[2*h+1][0] = r1;
                bl[2*h][1] = r2; bl[2*h+1][1] = r3;
            }
            // A fragments: 4 m-atoms, hi+lo
            u32 ah[4][4], al[4][4];
#pragma unroll
            for (int mi = 0; mi < 4; mi++) {
                const int rowA = warpM + mi * 16 + lrow;
                ldm_x4(lm_addr(tAh, rowA, ks, khalf),
                       ah[mi][0], ah[mi][1], ah[mi][2], ah[mi][3]);
                ldm_x4(lm_addr(tAl, rowA, ks, khalf),
                       al[mi][0], al[mi][1], al[mi][2], al[mi][3]);
            }
#pragma unroll
            for (int mi = 0; mi < 4; mi++)
#pragma unroll
                for (int ni = 0; ni < 4; ni++) {
                    mma_bf16(acc[mi][ni], ah[mi], bh[ni]);  // hi*hi
                    mma_bf16(acc[mi][ni], ah[mi], bl[ni]);  // hi*lo
                    mma_bf16(acc[mi][ni], al[mi], bh[ni]);  // lo*hi
                }
        }
        __syncthreads();
    }

    // ---- epilogue ----
    const int g  = lane >> 2;       // 0..7
    const int tc = (lane & 3) * 2;  // 0,2,4,6
#pragma unroll
    for (int mi = 0; mi < 4; mi++) {
#pragma unroll
        for (int h = 0; h < 2; h++) {
            const int row = row0 + warpM + mi * 16 + g + h * 8;
            if (!SPLIT_OUT) {
                float* crow = Cf + (size_t)blockIdx.z * sC + (size_t)row * N + col0 + warpN;
#pragma unroll
                for (int ni = 0; ni < 4; ni++) {
                    float2 v = make_float2(alpha * acc[mi][ni][h*2],
                                           alpha * acc[mi][ni][h*2+1]);
                    *(float2*)(crow + ni * 8 + tc) = v;
                }
            } else {
                const size_t ob = (size_t)blockIdx.z * sC + (size_t)row * N + col0 + warpN;
#pragma unroll
                for (int ni = 0; ni < 4; ni++) {
                    u32 hh, ll;
                    split2(alpha * acc[mi][ni][h*2], alpha * acc[mi][ni][h*2+1], hh, ll);
                    *(u32*)(Ch + ob + ni * 8 + tc) = hh;
                    *(u32*)(Cl + ob + ni * 8 + tc) = ll;
                }
            }
        }
    }
}

// ---------------- fp32 -> split bf16 (elementwise) ----------------
__global__ __launch_bounds__(256) void convert_split(
    const float* __restrict__ in, u16* __restrict__ hi, u16* __restrict__ lo, size_t n)
{
    size_t i = ((size_t)blockIdx.x * blockDim.x + threadIdx.x) * 4;
    if (i >= n) return;
    float4 v = *(const float4*)(in + i);
    u32 h0, l0, h1, l1;
    split2(v.x, v.y, h0, l0);
    split2(v.z, v.w, h1, l1);
    *(uint2*)(hi + i) = make_uint2(h0, h1);
    *(uint2*)(lo + i) = make_uint2(l0, l1);
}

// ---------------- transpose + split convert: out[c][r] = in[r][c] ----------------
__global__ __launch_bounds__(256) void transpose_convert(
    const float* __restrict__ in, u16* __restrict__ oh, u16* __restrict__ ol,
    int R, int C)
{
    __shared__ float t[32][33];
    in += (size_t)blockIdx.z * R * C;
    oh += (size_t)blockIdx.z * R * C;
    ol += (size_t)blockIdx.z * R * C;
    const int c0 = blockIdx.x * 32, r0 = blockIdx.y * 32;
    const int tx = threadIdx.x & 31, ty = threadIdx.x >> 5;
#pragma unroll
    for (int j = 0; j < 32; j += 8)
        t[ty + j][tx] = in[(size_t)(r0 + ty + j) * C + c0 + tx];
    __syncthreads();
#pragma unroll
    for (int j = 0; j < 32; j += 8) {
        float v = t[tx][ty + j];
        __nv_bfloat16 h = __float2bfloat16_rn(v);
        __nv_bfloat16 l = __float2bfloat16_rn(v - __bfloat162float(h));
        size_t o = (size_t)(c0 + ty + j) * R + r0 + tx;
        oh[o] = __bfloat16_as_ushort(h);
        ol[o] = __bfloat16_as_ushort(l);
    }
}

// ---------------- row softmax: fp32 in, split bf16 out ----------------
__global__ __launch_bounds__(256) void softmax_kernel(
    const float* __restrict__ S, u16* __restrict__ Ph, u16* __restrict__ Pl)
{
    const size_t base = (size_t)blockIdx.x * SS;
    const int tid = threadIdx.x;
    __shared__ float red[32];

    float4 v0 = *(const float4*)(S + base + tid * 8);
    float4 v1 = *(const float4*)(S + base + tid * 8 + 4);

    float m = fmaxf(fmaxf(fmaxf(v0.x, v0.y), fmaxf(v0.z, v0.w)),
                    fmaxf(fmaxf(v1.x, v1.y), fmaxf(v1.z, v1.w)));
#pragma unroll
    for (int s = 16; s > 0; s >>= 1)
        m = fmaxf(m, __shfl_xor_sync(0xffffffff, m, s));
    if ((tid & 31) == 0) red[tid >> 5] = m;
    __syncthreads();
    {
        float t = red[tid & 7];
#pragma unroll
        for (int s = 4; s > 0; s >>= 1)
            t = fmaxf(t, __shfl_xor_sync(0xffffffff, t, s));
        m = t;
    }

    v0.x = __expf(v0.x - m); v0.y = __expf(v0.y - m);
    v0.z = __expf(v0.z - m); v0.w = __expf(v0.w - m);
    v1.x = __expf(v1.x - m); v1.y = __expf(v1.y - m);
    v1.z = __expf(v1.z - m); v1.w = __expf(v1.w - m);
    float sum = v0.x + v0.y + v0.z + v0.w + v1.x + v1.y + v1.z + v1.w;
#pragma unroll
    for (int s = 16; s > 0; s >>= 1)
        sum += __shfl_xor_sync(0xffffffff, sum, s);
    __syncthreads();
    if ((tid & 31) == 0) red[tid >> 5] = sum;
    __syncthreads();
    {
        float t = red[tid & 7];
#pragma unroll
        for (int s = 4; s > 0; s >>= 1)
            t += __shfl_xor_sync(0xffffffff, t, s);
        sum = t;
    }

    const float inv = 1.0f / sum;
    float f[8] = {v0.x * inv, v0.y * inv, v0.z * inv, v0.w * inv,
                  v1.x * inv, v1.y * inv, v1.z * inv, v1.w * inv};
    u32 h[4], l[4];
#pragma unroll
    for (int p = 0; p < 4; p++)
        split2(f[p*2], f[p*2+1], h[p], l[p]);
    *(uint4*)(Ph + base + tid * 8) = make_uint4(h[0], h[1], h[2], h[3]);
    *(uint4*)(Pl + base + tid * 8) = make_uint4(l[0], l[1], l[2], l[3]);
}

// ---------------- launch ----------------
extern "C" void kernel_launch(void* const* d_in, const int* in_sizes, int n_in,
                              void* d_out, int out_size)
{
    const float* x   = (const float*)d_in[0];
    const float* W_q = (const float*)d_in[1];
    const float* W_k = (const float*)d_in[2];
    const float* W_v = (const float*)d_in[3];
    float* out = (float*)d_out;

    u16 *xh, *xl, *Wth, *Wtl, *Qh, *Ql, *Kh, *Kl, *Vth, *Vtl, *Ph, *Pl;
    float *V, *Sc;
    cudaGetSymbolAddress((void**)&xh,  g_xh);
    cudaGetSymbolAddress((void**)&xl,  g_xl);
    cudaGetSymbolAddress((void**)&Wth, g_Wth);
    cudaGetSymbolAddress((void**)&Wtl, g_Wtl);
    cudaGetSymbolAddress((void**)&Qh,  g_Qh);
    cudaGetSymbolAddress((void**)&Ql,  g_Ql);
    cudaGetSymbolAddress((void**)&Kh,  g_Kh);
    cudaGetSymbolAddress((void**)&Kl,  g_Kl);
    cudaGetSymbolAddress((void**)&V,   g_V);
    cudaGetSymbolAddress((void**)&Vth, g_Vth);
    cudaGetSymbolAddress((void**)&Vtl, g_Vtl);
    cudaGetSymbolAddress((void**)&Sc,  g_S);
    cudaGetSymbolAddress((void**)&Ph,  g_Ph);
    cudaGetSymbolAddress((void**)&Pl,  g_Pl);

    cudaFuncSetAttribute(gemm_mma<true>,  cudaFuncAttributeMaxDynamicSharedMemorySize, SMEM_BYTES);
    cudaFuncSetAttribute(gemm_mma<false>, cudaFuncAttributeMaxDynamicSharedMemorySize, SMEM_BYTES);

    const int M1 = BB * SS;  // 8192
    const float scale = 1.0f / sqrtf((float)UU);
    const size_t WSZ = (size_t)DD * UU;

    // 0) convert x -> split bf16
    {
        size_t n = (size_t)M1 * DD;
        convert_split<<<(unsigned)((n / 4 + 255) / 256), 256>>>(x, xh, xl, n);
    }
    // 0b) transpose+convert weights: Wt[u][d]
    {
        dim3 g(UU / 32, DD / 32, 1);
        transpose_convert<<<g, 256>>>(W_q, Wth + 0 * WSZ, Wtl + 0 * WSZ, DD, UU);
        transpose_convert<<<g, 256>>>(W_k, Wth + 1 * WSZ, Wtl + 1 * WSZ, DD, UU);
        transpose_convert<<<g, 256>>>(W_v, Wth + 2 * WSZ, Wtl + 2 * WSZ, DD, UU);
    }

    // 1) projections: Q,K split-out; V fp32 (for transpose)
    {
        dim3 g(UU / 128, M1 / 128, 1);
        gemm_mma<true><<<g, 256, SMEM_BYTES>>>(xh, xl, Wth + 0 * WSZ, Wtl + 0 * WSZ,
                                               nullptr, Qh, Ql, M1, UU, DD, 0, 0, 0, 1.0f);
        gemm_mma<true><<<g, 256, SMEM_BYTES>>>(xh, xl, Wth + 1 * WSZ, Wtl + 1 * WSZ,
                                               nullptr, Kh, Kl, M1, UU, DD, 0, 0, 0, 1.0f);
        gemm_mma<false><<<g, 256, SMEM_BYTES>>>(xh, xl, Wth + 2 * WSZ, Wtl + 2 * WSZ,
                                                V, nullptr, nullptr, M1, UU, DD, 0, 0, 0, 1.0f);
    }

    // 2) transpose+convert V per batch: Vt[b][u][s]
    {
        dim3 g(UU / 32, SS / 32, BB);
        transpose_convert<<<g, 256>>>(V, Vth, Vtl, SS, UU);
    }

    // 3) scores = scale * Q K^T  -> fp32
    {
        dim3 g(SS / 128, SS / 128, BB);
        gemm_mma<false><<<g, 256, SMEM_BYTES>>>(Qh, Ql, Kh, Kl, Sc, nullptr, nullptr,
                                                SS, SS, UU,
                                                (size_t)SS * UU, (size_t)SS * UU, (size_t)SS * SS,
                                                scale);
    }

    // 4) softmax rows -> split bf16 attn
    softmax_kernel<<<BB * SS, 256>>>(Sc, Ph, Pl);

    // 5) out = attn * Vt (NT) -> fp32 to d_out
    {
        dim3 g(UU / 128, SS / 128, BB);
        gemm_mma<false><<<g, 256, SMEM_BYTES>>>(Ph, Pl, Vth, Vtl, out, nullptr, nullptr,
                                                SS, UU, SS,
                                                (size_t)SS * SS, (size_t)SS * UU, (size_t)SS * UU,
                                                1.0f);
    }
}

// round 11
// speedup vs baseline: 2.3279x; 1.0554x over previous
#include <cuda_runtime.h>
#include <cuda_bf16.h>
#include <math.h>

// Problem dims (fixed per reference)
#define BB 4
#define SS 2048
#define DD 768
#define UU 768

typedef unsigned short u16;
typedef unsigned int   u32;

// ---------------- scratch (no allocations allowed) ----------------
__device__ u16   g_xh [(size_t)BB*SS*DD];
__device__ u16   g_xl [(size_t)BB*SS*DD];
__device__ u16   g_Wth[(size_t)3*DD*UU];
__device__ u16   g_Wtl[(size_t)3*DD*UU];
__device__ u16   g_Qh [(size_t)BB*SS*UU];
__device__ u16   g_Ql [(size_t)BB*SS*UU];
__device__ u16   g_Kh [(size_t)BB*SS*UU];
__device__ u16   g_Kl [(size_t)BB*SS*UU];
__device__ float g_V  [(size_t)BB*SS*UU];
__device__ u16   g_Vth[(size_t)BB*SS*UU];
__device__ u16   g_Vtl[(size_t)BB*SS*UU];
__device__ float g_S  [(size_t)BB*SS*SS];
__device__ u16   g_Ph [(size_t)BB*SS*SS];
__device__ u16   g_Pl [(size_t)BB*SS*SS];

// ---------------- helpers ----------------
__device__ __forceinline__ u32 s2u(const void* p) {
    u32 a;
    asm("{ .reg .u64 t; cvta.to.shared.u64 t, %1; cvt.u32.u64 %0, t; }"
        : "=r"(a) : "l"(p));
    return a;
}

__device__ __forceinline__ void cpasync16(u32 dst, const void* src) {
    asm volatile("cp.async.cg.shared.global [%0], [%1], 16;"
                 :: "r"(dst), "l"(src) : "memory");
}
__device__ __forceinline__ void cp_commit() {
    asm volatile("cp.async.commit_group;" ::: "memory");
}
template <int N>
__device__ __forceinline__ void cp_wait() {
    asm volatile("cp.async.wait_group %0;" :: "n"(N) : "memory");
}

__device__ __forceinline__ void ldm_x4(u32 addr, u32& r0, u32& r1, u32& r2, u32& r3) {
    asm volatile("ldmatrix.sync.aligned.m8n8.x4.shared.b16 {%0,%1,%2,%3}, [%4];"
                 : "=r"(r0), "=r"(r1), "=r"(r2), "=r"(r3) : "r"(addr));
}

__device__ __forceinline__ void mma_bf16(float* c, const u32* a, const u32* b) {
    asm volatile(
        "mma.sync.aligned.m16n8k16.row.col.f32.bf16.bf16.f32 "
        "{%0,%1,%2,%3}, {%4,%5,%6,%7}, {%8,%9}, {%0,%1,%2,%3};\n"
        : "+f"(c[0]), "+f"(c[1]), "+f"(c[2]), "+f"(c[3])
        : "r"(a[0]), "r"(a[1]), "r"(a[2]), "r"(a[3]), "r"(b[0]), "r"(b[1]));
}

__device__ __forceinline__ void split2(float a, float b, u32& h, u32& l) {
    __nv_bfloat16 ah = __float2bfloat16_rn(a), bh = __float2bfloat16_rn(b);
    __nv_bfloat16 al = __float2bfloat16_rn(a - __bfloat162float(ah));
    __nv_bfloat16 bl = __float2bfloat16_rn(b - __bfloat162float(bh));
    h = (u32)__bfloat16_as_ushort(ah) | ((u32)__bfloat16_as_ushort(bh) << 16);
    l = (u32)__bfloat16_as_ushort(al) | ((u32)__bfloat16_as_ushort(bl) << 16);
}

// =============================================================
// mma.sync bf16x2 GEMM (NT): C[M,N] = alpha * A[M,K] * B[N,K]^T
// Split hi/lo bf16 inputs. 128x128 block tile, K-chunk 32
// (64B rows, custom swizzle), 3-stage cp.async pipeline,
// 2 CTAs/SM, ldmatrix.x4 fragments, 8 warps (2x4),
// warp tile 64x32, 3 mma terms per k16 step.
// =============================================================
#define KC 32
#define TILEB 8192            // 128 rows * 64 B
#define BUFB  (4 * TILEB)     // AH, AL, BH, BL  (32 KB)
#define STAGES 3
#define SMEM_BYTES (STAGES * BUFB)   // 98304

// 64B-row swizzle: off = r*64 + c*16  ->  off ^ (((r>>1)&7)<<4)
__device__ __forceinline__ u32 sw32(int row, int chunk) {
    u32 off = (u32)row * 64u + (u32)chunk * 16u;
    return off ^ ((((u32)row >> 1) & 7u) << 4);
}
__device__ __forceinline__ u32 lm_addr(u32 tile, int row, int ks, int khalf) {
    return tile + sw32(row, (ks << 1) | khalf);
}

template <bool SPLIT_OUT>
__global__ __launch_bounds__(256, 2) void gemm_mma(
    const u16* __restrict__ Ah, const u16* __restrict__ Al,
    const u16* __restrict__ Bh, const u16* __restrict__ Bl,
    float* __restrict__ Cf, u16* __restrict__ Ch, u16* __restrict__ Cl,
    int M, int N, int K,
    size_t sA, size_t sB, size_t sC, float alpha)
{
    extern __shared__ __align__(1024) char smem[];
    const u32 sb = s2u(smem);
    const int tid  = threadIdx.x;
    const int lane = tid & 31;
    const int warp = tid >> 5;

    Ah += (size_t)blockIdx.z * sA;  Al += (size_t)blockIdx.z * sA;
    Bh += (size_t)blockIdx.z * sB;  Bl += (size_t)blockIdx.z * sB;

    const int row0 = blockIdx.y * 128;
    const int col0 = blockIdx.x * 128;

    const int warpM = (warp >> 2) * 64;   // 2 warps along M
    const int warpN = (warp & 3) * 32;    // 4 warps along N
    const int lrow  = lane & 15;
    const int khalf = lane >> 4;

    // ---- staging geometry: 2 threads/row, 32B each (2x 16B chunks) ----
    const int r    = tid >> 1;
    const int half = tid & 1;
    const u32 sw0 = sw32(r, 2 * half);
    const u32 sw1 = sw32(r, 2 * half + 1);
    const u16* gAh = Ah + (size_t)(row0 + r) * K + half * 16;
    const u16* gAl = Al + (size_t)(row0 + r) * K + half * 16;
    const u16* gBh = Bh + (size_t)(col0 + r) * K + half * 16;
    const u16* gBl = Bl + (size_t)(col0 + r) * K + half * 16;

    const int nC = K / KC;

    auto load_chunk = [&](int c, int slot) {
        const u32 tb = sb + (u32)slot * BUFB;
        const int ko = c * KC;
        cpasync16(tb + 0 * TILEB + sw0, gAh + ko);
        cpasync16(tb + 0 * TILEB + sw1, gAh + ko + 8);
        cpasync16(tb + 1 * TILEB + sw0, gAl + ko);
        cpasync16(tb + 1 * TILEB + sw1, gAl + ko + 8);
        cpasync16(tb + 2 * TILEB + sw0, gBh + ko);
        cpasync16(tb + 2 * TILEB + sw1, gBh + ko + 8);
        cpasync16(tb + 3 * TILEB + sw0, gBl + ko);
        cpasync16(tb + 3 * TILEB + sw1, gBl + ko + 8);
    };

    float acc[4][4][4] = {};

    load_chunk(0, 0); cp_commit();
    load_chunk(1, 1); cp_commit();

    for (int c = 0; c < nC; c++) {
        const int slot = c % STAGES;

        cp_wait<1>();
        __syncthreads();

        if (c + 2 < nC)
            load_chunk(c + 2, (c + 2) % STAGES);
        cp_commit();

        const u32 tAh = sb + (u32)slot * BUFB;
        const u32 tAl = tAh + TILEB;
        const u32 tBh = tAh + 2 * TILEB;
        const u32 tBl = tAh + 3 * TILEB;

#pragma unroll
        for (int ks = 0; ks < 2; ks++) {
            u32 bh[4][2], bl[4][2];
#pragma unroll
            for (int h = 0; h < 2; h++) {
                const int rowB = warpN + h * 16 + lrow;
                u32 r0, r1, r2, r3;
                ldm_x4(lm_addr(tBh, rowB, ks, khalf), r0, r1, r2, r3);
                bh[2*h][0] = r0; bh[2*h+1][0] = r1;
                bh[2*h][1] = r2; bh[2*h+1][1] = r3;
                ldm_x4(lm_addr(tBl, rowB, ks, khalf), r0, r1, r2, r3);
                bl[2*h][0] = r0; bl[2*h+1][0] = r1;
                bl[2*h][1] = r2; bl[2*h+1][1] = r3;
            }
#pragma unroll
            for (int mi = 0; mi < 4; mi++) {
                const int rowA = warpM + mi * 16 + lrow;
                u32 ah[4], al[4];
                ldm_x4(lm_addr(tAh, rowA, ks, khalf), ah[0], ah[1], ah[2], ah[3]);
                ldm_x4(lm_addr(tAl, rowA, ks, khalf), al[0], al[1], al[2], al[3]);
#pragma unroll
                for (int ni = 0; ni < 4; ni++) {
                    mma_bf16(acc[mi][ni], ah, bh[ni]);  // hi*hi
                    mma_bf16(acc[mi][ni], ah, bl[ni]);  // hi*lo
                    mma_bf16(acc[mi][ni], al, bh[ni]);  // lo*hi
                }
            }
        }
        __syncthreads();
    }

    // ---- epilogue ----
    const int g  = lane >> 2;
    const int tc = (lane & 3) * 2;
#pragma unroll
    for (int mi = 0; mi < 4; mi++) {
#pragma unroll
        for (int h = 0; h < 2; h++) {
            const int row = row0 + warpM + mi * 16 + g + h * 8;
            if (!SPLIT_OUT) {
                float* crow = Cf + (size_t)blockIdx.z * sC + (size_t)row * N + col0 + warpN;
#pragma unroll
                for (int ni = 0; ni < 4; ni++) {
                    float2 v = make_float2(alpha * acc[mi][ni][h*2],
                                           alpha * acc[mi][ni][h*2+1]);
                    *(float2*)(crow + ni * 8 + tc) = v;
                }
            } else {
                const size_t ob = (size_t)blockIdx.z * sC + (size_t)row * N + col0 + warpN;
#pragma unroll
                for (int ni = 0; ni < 4; ni++) {
                    u32 hh, ll;
                    split2(alpha * acc[mi][ni][h*2], alpha * acc[mi][ni][h*2+1], hh, ll);
                    *(u32*)(Ch + ob + ni * 8 + tc) = hh;
                    *(u32*)(Cl + ob + ni * 8 + tc) = ll;
                }
            }
        }
    }
}

// ---------------- fp32 -> split bf16 (elementwise) ----------------
__global__ __launch_bounds__(256) void convert_split(
    const float* __restrict__ in, u16* __restrict__ hi, u16* __restrict__ lo, size_t n)
{
    size_t i = ((size_t)blockIdx.x * blockDim.x + threadIdx.x) * 4;
    if (i >= n) return;
    float4 v = *(const float4*)(in + i);
    u32 h0, l0, h1, l1;
    split2(v.x, v.y, h0, l0);
    split2(v.z, v.w, h1, l1);
    *(uint2*)(hi + i) = make_uint2(h0, h1);
    *(uint2*)(lo + i) = make_uint2(l0, l1);
}

// ---------------- transpose + split convert: out[c][r] = in[r][c] ----------------
__global__ __launch_bounds__(256) void transpose_convert(
    const float* __restrict__ in, u16* __restrict__ oh, u16* __restrict__ ol,
    int R, int C)
{
    __shared__ float t[32][33];
    in += (size_t)blockIdx.z * R * C;
    oh += (size_t)blockIdx.z * R * C;
    ol += (size_t)blockIdx.z * R * C;
    const int c0 = blockIdx.x * 32, r0 = blockIdx.y * 32;
    const int tx = threadIdx.x & 31, ty = threadIdx.x >> 5;
#pragma unroll
    for (int j = 0; j < 32; j += 8)
        t[ty + j][tx] = in[(size_t)(r0 + ty + j) * C + c0 + tx];
    __syncthreads();
#pragma unroll
    for (int j = 0; j < 32; j += 8) {
        float v = t[tx][ty + j];
        __nv_bfloat16 h = __float2bfloat16_rn(v);
        __nv_bfloat16 l = __float2bfloat16_rn(v - __bfloat162float(h));
        size_t o = (size_t)(c0 + ty + j) * R + r0 + tx;
        oh[o] = __bfloat16_as_ushort(h);
        ol[o] = __bfloat16_as_ushort(l);
    }
}

// ---------------- row softmax: fp32 in, split bf16 out ----------------
__global__ __launch_bounds__(256) void softmax_kernel(
    const float* __restrict__ S, u16* __restrict__ Ph, u16* __restrict__ Pl)
{
    const size_t base = (size_t)blockIdx.x * SS;
    const int tid = threadIdx.x;
    __shared__ float red[32];

    float4 v0 = *(const float4*)(S + base + tid * 8);
    float4 v1 = *(const float4*)(S + base + tid * 8 + 4);

    float m = fmaxf(fmaxf(fmaxf(v0.x, v0.y), fmaxf(v0.z, v0.w)),
                    fmaxf(fmaxf(v1.x, v1.y), fmaxf(v1.z, v1.w)));
#pragma unroll
    for (int s = 16; s > 0; s >>= 1)
        m = fmaxf(m, __shfl_xor_sync(0xffffffff, m, s));
    if ((tid & 31) == 0) red[tid >> 5] = m;
    __syncthreads();
    {
        float t = red[tid & 7];
#pragma unroll
        for (int s = 4; s > 0; s >>= 1)
            t = fmaxf(t, __shfl_xor_sync(0xffffffff, t, s));
        m = t;
    }

    v0.x = __expf(v0.x - m); v0.y = __expf(v0.y - m);
    v0.z = __expf(v0.z - m); v0.w = __expf(v0.w - m);
    v1.x = __expf(v1.x - m); v1.y = __expf(v1.y - m);
    v1.z = __expf(v1.z - m); v1.w = __expf(v1.w - m);
    float sum = v0.x + v0.y + v0.z + v0.w + v1.x + v1.y + v1.z + v1.w;
#pragma unroll
    for (int s = 16; s > 0; s >>= 1)
        sum += __shfl_xor_sync(0xffffffff, sum, s);
    __syncthreads();
    if ((tid & 31) == 0) red[tid >> 5] = sum;
    __syncthreads();
    {
        float t = red[tid & 7];
#pragma unroll
        for (int s = 4; s > 0; s >>= 1)
            t += __shfl_xor_sync(0xffffffff, t, s);
        sum = t;
    }

    const float inv = 1.0f / sum;
    float f[8] = {v0.x * inv, v0.y * inv, v0.z * inv, v0.w * inv,
                  v1.x * inv, v1.y * inv, v1.z * inv, v1.w * inv};
    u32 h[4], l[4];
#pragma unroll
    for (int p = 0; p < 4; p++)
        split2(f[p*2], f[p*2+1], h[p], l[p]);
    *(uint4*)(Ph + base + tid * 8) = make_uint4(h[0], h[1], h[2], h[3]);
    *(uint4*)(Pl + base + tid * 8) = make_uint4(l[0], l[1], l[2], l[3]);
}

// ---------------- launch ----------------
extern "C" void kernel_launch(void* const* d_in, const int* in_sizes, int n_in,
                              void* d_out, int out_size)
{
    const float* x   = (const float*)d_in[0];
    const float* W_q = (const float*)d_in[1];
    const float* W_k = (const float*)d_in[2];
    const float* W_v = (const float*)d_in[3];
    float* out = (float*)d_out;

    u16 *xh, *xl, *Wth, *Wtl, *Qh, *Ql, *Kh, *Kl, *Vth, *Vtl, *Ph, *Pl;
    float *V, *Sc;
    cudaGetSymbolAddress((void**)&xh,  g_xh);
    cudaGetSymbolAddress((void**)&xl,  g_xl);
    cudaGetSymbolAddress((void**)&Wth, g_Wth);
    cudaGetSymbolAddress((void**)&Wtl, g_Wtl);
    cudaGetSymbolAddress((void**)&Qh,  g_Qh);
    cudaGetSymbolAddress((void**)&Ql,  g_Ql);
    cudaGetSymbolAddress((void**)&Kh,  g_Kh);
    cudaGetSymbolAddress((void**)&Kl,  g_Kl);
    cudaGetSymbolAddress((void**)&V,   g_V);
    cudaGetSymbolAddress((void**)&Vth, g_Vth);
    cudaGetSymbolAddress((void**)&Vtl, g_Vtl);
    cudaGetSymbolAddress((void**)&Sc,  g_S);
    cudaGetSymbolAddress((void**)&Ph,  g_Ph);
    cudaGetSymbolAddress((void**)&Pl,  g_Pl);

    cudaFuncSetAttribute(gemm_mma<true>,  cudaFuncAttributeMaxDynamicSharedMemorySize, SMEM_BYTES);
    cudaFuncSetAttribute(gemm_mma<false>, cudaFuncAttributeMaxDynamicSharedMemorySize, SMEM_BYTES);

    const int M1 = BB * SS;  // 8192
    const float scale = 1.0f / sqrtf((float)UU);
    const size_t WSZ = (size_t)DD * UU;

    // 0) convert x -> split bf16
    {
        size_t n = (size_t)M1 * DD;
        convert_split<<<(unsigned)((n / 4 + 255) / 256), 256>>>(x, xh, xl, n);
    }
    // 0b) transpose+convert weights: Wt[u][d]
    {
        dim3 g(UU / 32, DD / 32, 1);
        transpose_convert<<<g, 256>>>(W_q, Wth + 0 * WSZ, Wtl + 0 * WSZ, DD, UU);
        transpose_convert<<<g, 256>>>(W_k, Wth + 1 * WSZ, Wtl + 1 * WSZ, DD, UU);
        transpose_convert<<<g, 256>>>(W_v, Wth + 2 * WSZ, Wtl + 2 * WSZ, DD, UU);
    }

    // 1) projections: Q,K split-out; V fp32 (for transpose)
    {
        dim3 g(UU / 128, M1 / 128, 1);
        gemm_mma<true><<<g, 256, SMEM_BYTES>>>(xh, xl, Wth + 0 * WSZ, Wtl + 0 * WSZ,
                                               nullptr, Qh, Ql, M1, UU, DD, 0, 0, 0, 1.0f);
        gemm_mma<true><<<g, 256, SMEM_BYTES>>>(xh, xl, Wth + 1 * WSZ, Wtl + 1 * WSZ,
                                               nullptr, Kh, Kl, M1, UU, DD, 0, 0, 0, 1.0f);
        gemm_mma<false><<<g, 256, SMEM_BYTES>>>(xh, xl, Wth + 2 * WSZ, Wtl + 2 * WSZ,
                                                V, nullptr, nullptr, M1, UU, DD, 0, 0, 0, 1.0f);
    }

    // 2) transpose+convert V per batch: Vt[b][u][s]
    {
        dim3 g(UU / 32, SS / 32, BB);
        transpose_convert<<<g, 256>>>(V, Vth, Vtl, SS, UU);
    }

    // 3) scores = scale * Q K^T  -> fp32
    {
        dim3 g(SS / 128, SS / 128, BB);
        gemm_mma<false><<<g, 256, SMEM_BYTES>>>(Qh, Ql, Kh, Kl, Sc, nullptr, nullptr,
                                                SS, SS, UU,
                                                (size_t)SS * UU, (size_t)SS * UU, (size_t)SS * SS,
                                                scale);
    }

    // 4) softmax rows -> split bf16 attn
    softmax_kernel<<<BB * SS, 256>>>(Sc, Ph, Pl);

    // 5) out = attn * Vt (NT) -> fp32 to d_out
    {
        dim3 g(UU / 128, SS / 128, BB);
        gemm_mma<false><<<g, 256, SMEM_BYTES>>>(Ph, Pl, Vth, Vtl, out, nullptr, nullptr,
                                                SS, UU, SS,
                                                (size_t)SS * SS, (size_t)SS * UU, (size_t)SS * UU,
                                                1.0f);
    }
}

// round 14
// speedup vs baseline: 2.4850x; 1.0675x over previous
#include <cuda_runtime.h>
#include <cuda_bf16.h>
#include <math.h>

// Problem dims (fixed per reference)
#define BB 4
#define SS 2048
#define DD 768
#define UU 768

typedef unsigned short u16;
typedef unsigned int   u32;

// ---------------- scratch (no allocations allowed) ----------------
__device__ u16   g_xh [(size_t)BB*SS*DD];
__device__ u16   g_xl [(size_t)BB*SS*DD];
__device__ u16   g_Wth[(size_t)3*DD*UU];
__device__ u16   g_Wtl[(size_t)3*DD*UU];
__device__ u16   g_Qh [(size_t)BB*SS*UU];
__device__ u16   g_Ql [(size_t)BB*SS*UU];
__device__ u16   g_Kh [(size_t)BB*SS*UU];
__device__ u16   g_Kl [(size_t)BB*SS*UU];
__device__ float g_V  [(size_t)BB*SS*UU];
__device__ u16   g_Vth[(size_t)BB*SS*UU];
__device__ u16   g_Vtl[(size_t)BB*SS*UU];
__device__ float g_S  [(size_t)BB*SS*SS];
__device__ u16   g_Ph [(size_t)BB*SS*SS];
__device__ u16   g_Pl [(size_t)BB*SS*SS];

// ---------------- helpers ----------------
__device__ __forceinline__ u32 s2u(const void* p) {
    u32 a;
    asm("{ .reg .u64 t; cvta.to.shared.u64 t, %1; cvt.u32.u64 %0, t; }"
        : "=r"(a) : "l"(p));
    return a;
}

__device__ __forceinline__ void cpasync16(u32 dst, const void* src) {
    asm volatile("cp.async.cg.shared.global [%0], [%1], 16;"
                 :: "r"(dst), "l"(src) : "memory");
}
__device__ __forceinline__ void cp_commit() {
    asm volatile("cp.async.commit_group;" ::: "memory");
}
template <int N>
__device__ __forceinline__ void cp_wait() {
    asm volatile("cp.async.wait_group %0;" :: "n"(N) : "memory");
}

__device__ __forceinline__ void ldm_x4(u32 addr, u32& r0, u32& r1, u32& r2, u32& r3) {
    asm volatile("ldmatrix.sync.aligned.m8n8.x4.shared.b16 {%0,%1,%2,%3}, [%4];"
                 : "=r"(r0), "=r"(r1), "=r"(r2), "=r"(r3) : "r"(addr));
}

__device__ __forceinline__ void mma_bf16(float* c, const u32* a, const u32* b) {
    asm volatile(
        "mma.sync.aligned.m16n8k16.row.col.f32.bf16.bf16.f32 "
        "{%0,%1,%2,%3}, {%4,%5,%6,%7}, {%8,%9}, {%0,%1,%2,%3};\n"
        : "+f"(c[0]), "+f"(c[1]), "+f"(c[2]), "+f"(c[3])
        : "r"(a[0]), "r"(a[1]), "r"(a[2]), "r"(a[3]), "r"(b[0]), "r"(b[1]));
}

__device__ __forceinline__ void split2(float a, float b, u32& h, u32& l) {
    __nv_bfloat16 ah = __float2bfloat16_rn(a), bh = __float2bfloat16_rn(b);
    __nv_bfloat16 al = __float2bfloat16_rn(a - __bfloat162float(ah));
    __nv_bfloat16 bl = __float2bfloat16_rn(b - __bfloat162float(bh));
    h = (u32)__bfloat16_as_ushort(ah) | ((u32)__bfloat16_as_ushort(bh) << 16);
    l = (u32)__bfloat16_as_ushort(al) | ((u32)__bfloat16_as_ushort(bl) << 16);
}

// =============================================================
// mma.sync bf16x2 GEMM (NT): C[M,N] = alpha * A[M,K] * B[N,K]^T
// Split hi/lo bf16 inputs. Block tile (MIA*32) x 128, K-chunk 32
// (64B rows, swizzled), 3-stage cp.async pipeline, 2 CTAs/SM,
// ldmatrix.x4 fragments, 8 warps (2xM, 4xN), 3 mma terms/k16.
// OUT: 0 = fp32 C, 1 = split bf16 C, 2 = fused QKV routing.
// =============================================================
#define KC 32
#define STAGES 3

__device__ __forceinline__ u32 sw32(int row, int chunk) {
    u32 off = (u32)row * 64u + (u32)chunk * 16u;
    return off ^ ((((u32)row >> 1) & 7u) << 4);
}
__device__ __forceinline__ u32 lm_addr(u32 tile, int row, int ks, int khalf) {
    return tile + sw32(row, (ks << 1) | khalf);
}

template <int MIA, int OUT>   // MIA: m16-atoms per warp (BM = MIA*32)
__global__ __launch_bounds__(256, 2) void gemm_mma(
    const u16* __restrict__ Ah, const u16* __restrict__ Al,
    const u16* __restrict__ Bh, const u16* __restrict__ Bl,
    float* __restrict__ Cf, u16* __restrict__ Ch, u16* __restrict__ Cl,
    u16* __restrict__ Ch2, u16* __restrict__ Cl2,
    int M, int N, int K,
    size_t sA, size_t sB, size_t sC, float alpha)
{
    constexpr int BM    = MIA * 32;
    constexpr int TILEA = BM * 64;     // bytes per A array per stage
    constexpr int TILEBB = 128 * 64;   // bytes per B array per stage
    constexpr int BUF   = 2 * TILEA + 2 * TILEBB;

    extern __shared__ __align__(1024) char smem[];
    const u32 sb = s2u(smem);
    const int tid  = threadIdx.x;
    const int lane = tid & 31;
    const int warp = tid >> 5;

    Ah += (size_t)blockIdx.z * sA;  Al += (size_t)blockIdx.z * sA;
    Bh += (size_t)blockIdx.z * sB;  Bl += (size_t)blockIdx.z * sB;

    const int row0 = blockIdx.y * BM;
    const int col0 = blockIdx.x * 128;

    const int warpM = (warp >> 2) * (BM / 2);  // 2 warps along M
    const int warpN = (warp & 3) * 32;         // 4 warps along N
    const int lrow  = lane & 15;
    const int khalf = lane >> 4;

    // ---- staging geometry ----
    // B: 128 rows, 2 thr/row, 2 x 16B chunks each
    const int rB   = tid >> 1;
    const int hB   = tid & 1;
    const u32 swB0 = sw32(rB, 2 * hB);
    const u32 swB1 = sw32(rB, 2 * hB + 1);
    const u16* gBh = Bh + (size_t)(col0 + rB) * K + hB * 16;
    const u16* gBl = Bl + (size_t)(col0 + rB) * K + hB * 16;

    // A: BM rows
    //  MIA==4: 2 thr/row, 2 chunks each;  MIA==2: 4 thr/row, 1 chunk each
    const int rA   = (MIA == 4) ? (tid >> 1) : (tid >> 2);
    const int cA   = (MIA == 4) ? 2 * (tid & 1) : (tid & 3);
    const u32 swA0 = sw32(rA, cA);
    const u32 swA1 = sw32(rA, cA + 1);   // used only when MIA==4
    const u16* gAh = Ah + (size_t)(row0 + rA) * K + cA * 8;
    const u16* gAl = Al + (size_t)(row0 + rA) * K + cA * 8;

    const int nC = K / KC;

    auto load_chunk = [&](int c, int slot) {
        const u32 tb = sb + (u32)slot * BUF;
        const int ko = c * KC;
        cpasync16(tb + swA0, gAh + ko);
        cpasync16(tb + TILEA + swA0, gAl + ko);
        if (MIA == 4) {
            cpasync16(tb + swA1, gAh + ko + 8);
            cpasync16(tb + TILEA + swA1, gAl + ko + 8);
        }
        const u32 tbB = tb + 2 * TILEA;
        cpasync16(tbB + swB0, gBh + ko);
        cpasync16(tbB + swB1, gBh + ko + 8);
        cpasync16(tbB + TILEBB + swB0, gBl + ko);
        cpasync16(tbB + TILEBB + swB1, gBl + ko + 8);
    };

    float acc[MIA][4][4] = {};

    load_chunk(0, 0); cp_commit();
    load_chunk(1, 1); cp_commit();

    for (int c = 0; c < nC; c++) {
        const int slot = c % STAGES;

        cp_wait<1>();
        __syncthreads();

        if (c + 2 < nC)
            load_chunk(c + 2, (c + 2) % STAGES);
        cp_commit();

        const u32 tAh = sb + (u32)slot * BUF;
        const u32 tAl = tAh + TILEA;
        const u32 tBh = tAh + 2 * TILEA;
        const u32 tBl = tBh + TILEBB;

#pragma unroll
        for (int ks = 0; ks < 2; ks++) {
            u32 bh[4][2], bl[4][2];
#pragma unroll
            for (int h = 0; h < 2; h++) {
                const int rowB = warpN + h * 16 + lrow;
                u32 r0, r1, r2, r3;
                ldm_x4(lm_addr(tBh, rowB, ks, khalf), r0, r1, r2, r3);
                bh[2*h][0] = r0; bh[2*h+1][0] = r1;
                bh[2*h][1] = r2; bh[2*h+1][1] = r3;
                ldm_x4(lm_addr(tBl, rowB, ks, khalf), r0, r1, r2, r3);
                bl[2*h][0] = r0; bl[2*h+1][0] = r1;
                bl[2*h][1] = r2; bl[2*h+1][1] = r3;
            }
#pragma unroll
            for (int mi = 0; mi < MIA; mi++) {
                const int rowA = warpM + mi * 16 + lrow;
                u32 ah[4], al[4];
                ldm_x4(lm_addr(tAh, rowA, ks, khalf), ah[0], ah[1], ah[2], ah[3]);
                ldm_x4(lm_addr(tAl, rowA, ks, khalf), al[0], al[1], al[2], al[3]);
#pragma unroll
                for (int ni = 0; ni < 4; ni++) {
                    mma_bf16(acc[mi][ni], ah, bh[ni]);  // hi*hi
                    mma_bf16(acc[mi][ni], ah, bl[ni]);  // hi*lo
                    mma_bf16(acc[mi][ni], al, bh[ni]);  // lo*hi
                }
            }
        }
        // trailing __syncthreads removed: the top barrier of iteration c+1
        // orders compute(c) before any warp loads into slot c%STAGES (chunk c+3).
    }

    // ---- epilogue ----
    const int g  = lane >> 2;
    const int tc = (lane & 3) * 2;

    // QKV routing (OUT==2): N-segments of 768 -> Q(split) | K(split) | V(fp32)
    int seg = 0, lcol = col0;
    if (OUT == 2) { seg = col0 / 768; lcol = col0 - seg * 768; }
    const int ostride = (OUT == 2) ? 768 : N;

#pragma unroll
    for (int mi = 0; mi < MIA; mi++) {
#pragma unroll
        for (int h = 0; h < 2; h++) {
            const int row = row0 + warpM + mi * 16 + g + h * 8;
            const size_t ob = (size_t)blockIdx.z * sC + (size_t)row * ostride + lcol + warpN;
            if (OUT == 0) {
#pragma unroll
                for (int ni = 0; ni < 4; ni++) {
                    float2 v = make_float2(alpha * acc[mi][ni][h*2],
                                           alpha * acc[mi][ni][h*2+1]);
                    *(float2*)(Cf + ob + ni * 8 + tc) = v;
                }
            } else if (OUT == 1) {
#pragma unroll
                for (int ni = 0; ni < 4; ni++) {
                    u32 hh, ll;
                    split2(alpha * acc[mi][ni][h*2], alpha * acc[mi][ni][h*2+1], hh, ll);
                    *(u32*)(Ch + ob + ni * 8 + tc) = hh;
                    *(u32*)(Cl + ob + ni * 8 + tc) = ll;
                }
            } else {  // OUT == 2
                if (seg == 2) {
#pragma unroll
                    for (int ni = 0; ni < 4; ni++) {
                        float2 v = make_float2(acc[mi][ni][h*2], acc[mi][ni][h*2+1]);
                        *(float2*)(Cf + ob + ni * 8 + tc) = v;
                    }
                } else {
                    u16* oh = (seg == 0) ? Ch : Ch2;
                    u16* ol = (seg == 0) ? Cl : Cl2;
#pragma unroll
                    for (int ni = 0; ni < 4; ni++) {
                        u32 hh, ll;
                        split2(acc[mi][ni][h*2], acc[mi][ni][h*2+1], hh, ll);
                        *(u32*)(oh + ob + ni * 8 + tc) = hh;
                        *(u32*)(ol + ob + ni * 8 + tc) = ll;
                    }
                }
            }
        }
    }
}

// ---------------- fp32 -> split bf16 (elementwise) ----------------
__global__ __launch_bounds__(256) void convert_split(
    const float* __restrict__ in, u16* __restrict__ hi, u16* __restrict__ lo, size_t n)
{
    size_t i = ((size_t)blockIdx.x * blockDim.x + threadIdx.x) * 4;
    if (i >= n) return;
    float4 v = *(const float4*)(in + i);
    u32 h0, l0, h1, l1;
    split2(v.x, v.y, h0, l0);
    split2(v.z, v.w, h1, l1);
    *(uint2*)(hi + i) = make_uint2(h0, h1);
    *(uint2*)(lo + i) = make_uint2(l0, l1);
}

// ---------------- transpose + split convert: out[c][r] = in[r][c] ----------------
__global__ __launch_bounds__(256) void transpose_convert(
    const float* __restrict__ in, u16* __restrict__ oh, u16* __restrict__ ol,
    int R, int C)
{
    __shared__ float t[32][33];
    in += (size_t)blockIdx.z * R * C;
    oh += (size_t)blockIdx.z * R * C;
    ol += (size_t)blockIdx.z * R * C;
    const int c0 = blockIdx.x * 32, r0 = blockIdx.y * 32;
    const int tx = threadIdx.x & 31, ty = threadIdx.x >> 5;
#pragma unroll
    for (int j = 0; j < 32; j += 8)
        t[ty + j][tx] = in[(size_t)(r0 + ty + j) * C + c0 + tx];
    __syncthreads();
#pragma unroll
    for (int j = 0; j < 32; j += 8) {
        float v = t[tx][ty + j];
        __nv_bfloat16 h = __float2bfloat16_rn(v);
        __nv_bfloat16 l = __float2bfloat16_rn(v - __bfloat162float(h));
        size_t o = (size_t)(c0 + ty + j) * R + r0 + tx;
        oh[o] = __bfloat16_as_ushort(h);
        ol[o] = __bfloat16_as_ushort(l);
    }
}

// ---------------- row softmax: fp32 in, split bf16 out ----------------
__global__ __launch_bounds__(256) void softmax_kernel(
    const float* __restrict__ S, u16* __restrict__ Ph, u16* __restrict__ Pl)
{
    const size_t base = (size_t)blockIdx.x * SS;
    const int tid = threadIdx.x;
    __shared__ float red[32];

    float4 v0 = *(const float4*)(S + base + tid * 8);
    float4 v1 = *(const float4*)(S + base + tid * 8 + 4);

    float m = fmaxf(fmaxf(fmaxf(v0.x, v0.y), fmaxf(v0.z, v0.w)),
                    fmaxf(fmaxf(v1.x, v1.y), fmaxf(v1.z, v1.w)));
#pragma unroll
    for (int s = 16; s > 0; s >>= 1)
        m = fmaxf(m, __shfl_xor_sync(0xffffffff, m, s));
    if ((tid & 31) == 0) red[tid >> 5] = m;
    __syncthreads();
    {
        float t = red[tid & 7];
#pragma unroll
        for (int s = 4; s > 0; s >>= 1)
            t = fmaxf(t, __shfl_xor_sync(0xffffffff, t, s));
        m = t;
    }

    v0.x = __expf(v0.x - m); v0.y = __expf(v0.y - m);
    v0.z = __expf(v0.z - m); v0.w = __expf(v0.w - m);
    v1.x = __expf(v1.x - m); v1.y = __expf(v1.y - m);
    v1.z = __expf(v1.z - m); v1.w = __expf(v1.w - m);
    float sum = v0.x + v0.y + v0.z + v0.w + v1.x + v1.y + v1.z + v1.w;
#pragma unroll
    for (int s = 16; s > 0; s >>= 1)
        sum += __shfl_xor_sync(0xffffffff, sum, s);
    __syncthreads();
    if ((tid & 31) == 0) red[tid >> 5] = sum;
    __syncthreads();
    {
        float t = red[tid & 7];
#pragma unroll
        for (int s = 4; s > 0; s >>= 1)
            t += __shfl_xor_sync(0xffffffff, t, s);
        sum = t;
    }

    const float inv = 1.0f / sum;
    float f[8] = {v0.x * inv, v0.y * inv, v0.z * inv, v0.w * inv,
                  v1.x * inv, v1.y * inv, v1.z * inv, v1.w * inv};
    u32 h[4], l[4];
#pragma unroll
    for (int p = 0; p < 4; p++)
        split2(f[p*2], f[p*2+1], h[p], l[p]);
    *(uint4*)(Ph + base + tid * 8) = make_uint4(h[0], h[1], h[2], h[3]);
    *(uint4*)(Pl + base + tid * 8) = make_uint4(l[0], l[1], l[2], l[3]);
}

// ---------------- launch ----------------
extern "C" void kernel_launch(void* const* d_in, const int* in_sizes, int n_in,
                              void* d_out, int out_size)
{
    const float* x   = (const float*)d_in[0];
    const float* W_q = (const float*)d_in[1];
    const float* W_k = (const float*)d_in[2];
    const float* W_v = (const float*)d_in[3];
    float* out = (float*)d_out;

    u16 *xh, *xl, *Wth, *Wtl, *Qh, *Ql, *Kh, *Kl, *Vth, *Vtl, *Ph, *Pl;
    float *V, *Sc;
    cudaGetSymbolAddress((void**)&xh,  g_xh);
    cudaGetSymbolAddress((void**)&xl,  g_xl);
    cudaGetSymbolAddress((void**)&Wth, g_Wth);
    cudaGetSymbolAddress((void**)&Wtl, g_Wtl);
    cudaGetSymbolAddress((void**)&Qh,  g_Qh);
    cudaGetSymbolAddress((void**)&Ql,  g_Ql);
    cudaGetSymbolAddress((void**)&Kh,  g_Kh);
    cudaGetSymbolAddress((void**)&Kl,  g_Kl);
    cudaGetSymbolAddress((void**)&V,   g_V);
    cudaGetSymbolAddress((void**)&Vth, g_Vth);
    cudaGetSymbolAddress((void**)&Vtl, g_Vtl);
    cudaGetSymbolAddress((void**)&Sc,  g_S);
    cudaGetSymbolAddress((void**)&Ph,  g_Ph);
    cudaGetSymbolAddress((void**)&Pl,  g_Pl);

    // smem sizes: MIA=4 -> 96 KB, MIA=2 -> 72 KB (3 stages)
    const int SM128 = STAGES * (2 * 128 * 64 + 2 * 128 * 64);  // 98304
    const int SM64  = STAGES * (2 * 64 * 64 + 2 * 128 * 64);   // 73728
    cudaFuncSetAttribute(gemm_mma<4,0>, cudaFuncAttributeMaxDynamicSharedMemorySize, SM128);
    cudaFuncSetAttribute(gemm_mma<4,2>, cudaFuncAttributeMaxDynamicSharedMemorySize, SM128);
    cudaFuncSetAttribute(gemm_mma<2,0>, cudaFuncAttributeMaxDynamicSharedMemorySize, SM64);

    const int M1 = BB * SS;  // 8192
    const float scale = 1.0f / sqrtf((float)UU);
    const size_t WSZ = (size_t)DD * UU;

    // 0) convert x -> split bf16
    {
        size_t n = (size_t)M1 * DD;
        convert_split<<<(unsigned)((n / 4 + 255) / 256), 256>>>(x, xh, xl, n);
    }
    // 0b) transpose+convert weights: Wt[u][d], stacked [Wq^T; Wk^T; Wv^T]
    {
        dim3 g(UU / 32, DD / 32, 1);
        transpose_convert<<<g, 256>>>(W_q, Wth + 0 * WSZ, Wtl + 0 * WSZ, DD, UU);
        transpose_convert<<<g, 256>>>(W_k, Wth + 1 * WSZ, Wtl + 1 * WSZ, DD, UU);
        transpose_convert<<<g, 256>>>(W_v, Wth + 2 * WSZ, Wtl + 2 * WSZ, DD, UU);
    }

    // 1) fused QKV projection: [8192,768] x [2304,768]^T, epilogue routes
    //    cols 0-767 -> Qh/Ql, 768-1535 -> Kh/Kl, 1536-2303 -> V (fp32)
    {
        dim3 g(3 * UU / 128, M1 / 128, 1);
        gemm_mma<4,2><<<g, 256, SM128>>>(xh, xl, Wth, Wtl,
                                         V, Qh, Ql, Kh, Kl,
                                         M1, 3 * UU, DD, 0, 0, 0, 1.0f);
    }

    // 2) transpose+convert V per batch: Vt[b][u][s]
    {
        dim3 g(UU / 32, SS / 32, BB);
        transpose_convert<<<g, 256>>>(V, Vth, Vtl, SS, UU);
    }

    // 3) scores = scale * Q K^T  -> fp32
    {
        dim3 g(SS / 128, SS / 128, BB);
        gemm_mma<4,0><<<g, 256, SM128>>>(Qh, Ql, Kh, Kl, Sc, nullptr, nullptr, nullptr, nullptr,
                                         SS, SS, UU,
                                         (size_t)SS * UU, (size_t)SS * UU, (size_t)SS * SS,
                                         scale);
    }

    // 4) softmax rows -> split bf16 attn
    softmax_kernel<<<BB * SS, 256>>>(Sc, Ph, Pl);

    // 5) out = attn * Vt (NT), BM=64 tile for better wave efficiency
    {
        dim3 g(UU / 128, SS / 64, BB);
        gemm_mma<2,0><<<g, 256, SM64>>>(Ph, Pl, Vth, Vtl, out, nullptr, nullptr, nullptr, nullptr,
                                        SS, UU, SS,
                                        (size_t)SS * SS, (size_t)SS * UU, (size_t)SS * UU,
                                        1.0f);
    }
}

// round 16
// speedup vs baseline: 2.9366x; 1.1817x over previous
#include <cuda_runtime.h>
#include <cuda_bf16.h>
#include <cuda_fp16.h>
#include <math.h>

// Problem dims (fixed per reference)
#define BB 4
#define SS 2048
#define DD 768
#define UU 768

typedef unsigned short u16;
typedef unsigned int   u32;

// ---------------- scratch (no allocations allowed) ----------------
__device__ u16   g_xh [(size_t)BB*SS*DD];
__device__ u16   g_xl [(size_t)BB*SS*DD];
__device__ u16   g_Wth[(size_t)3*DD*UU];
__device__ u16   g_Wtl[(size_t)3*DD*UU];
__device__ u16   g_Qh [(size_t)BB*SS*UU];
__device__ u16   g_Ql [(size_t)BB*SS*UU];
__device__ u16   g_Kh [(size_t)BB*SS*UU];
__device__ u16   g_Kl [(size_t)BB*SS*UU];
__device__ float g_V  [(size_t)BB*SS*UU];
__device__ u16   g_Vth[(size_t)BB*SS*UU];   // fp16 hi of V^T
__device__ float g_S  [(size_t)BB*SS*SS];
__device__ u16   g_Ph [(size_t)BB*SS*SS];   // fp16 hi of attn
__device__ u16   g_Pl [(size_t)BB*SS*SS];   // fp16 lo of attn

// ---------------- helpers ----------------
__device__ __forceinline__ u32 s2u(const void* p) {
    u32 a;
    asm("{ .reg .u64 t; cvta.to.shared.u64 t, %1; cvt.u32.u64 %0, t; }"
        : "=r"(a) : "l"(p));
    return a;
}

__device__ __forceinline__ void cpasync16(u32 dst, const void* src) {
    asm volatile("cp.async.cg.shared.global [%0], [%1], 16;"
                 :: "r"(dst), "l"(src) : "memory");
}
__device__ __forceinline__ void cp_commit() {
    asm volatile("cp.async.commit_group;" ::: "memory");
}
template <int N>
__device__ __forceinline__ void cp_wait() {
    asm volatile("cp.async.wait_group %0;" :: "n"(N) : "memory");
}

__device__ __forceinline__ void ldm_x4(u32 addr, u32& r0, u32& r1, u32& r2, u32& r3) {
    asm volatile("ldmatrix.sync.aligned.m8n8.x4.shared.b16 {%0,%1,%2,%3}, [%4];"
                 : "=r"(r0), "=r"(r1), "=r"(r2), "=r"(r3) : "r"(addr));
}

__device__ __forceinline__ void mma_bf16(float* c, const u32* a, const u32* b) {
    asm volatile(
        "mma.sync.aligned.m16n8k16.row.col.f32.bf16.bf16.f32 "
        "{%0,%1,%2,%3}, {%4,%5,%6,%7}, {%8,%9}, {%0,%1,%2,%3};\n"
        : "+f"(c[0]), "+f"(c[1]), "+f"(c[2]), "+f"(c[3])
        : "r"(a[0]), "r"(a[1]), "r"(a[2]), "r"(a[3]), "r"(b[0]), "r"(b[1]));
}

__device__ __forceinline__ void mma_f16(float* c, const u32* a, const u32* b) {
    asm volatile(
        "mma.sync.aligned.m16n8k16.row.col.f32.f16.f16.f32 "
        "{%0,%1,%2,%3}, {%4,%5,%6,%7}, {%8,%9}, {%0,%1,%2,%3};\n"
        : "+f"(c[0]), "+f"(c[1]), "+f"(c[2]), "+f"(c[3])
        : "r"(a[0]), "r"(a[1]), "r"(a[2]), "r"(a[3]), "r"(b[0]), "r"(b[1]));
}

__device__ __forceinline__ void split2(float a, float b, u32& h, u32& l) {
    __nv_bfloat16 ah = __float2bfloat16_rn(a), bh = __float2bfloat16_rn(b);
    __nv_bfloat16 al = __float2bfloat16_rn(a - __bfloat162float(ah));
    __nv_bfloat16 bl = __float2bfloat16_rn(b - __bfloat162float(bh));
    h = (u32)__bfloat16_as_ushort(ah) | ((u32)__bfloat16_as_ushort(bh) << 16);
    l = (u32)__bfloat16_as_ushort(al) | ((u32)__bfloat16_as_ushort(bl) << 16);
}

__device__ __forceinline__ void split2h(float a, float b, u32& h, u32& l) {
    __half ah = __float2half_rn(a), bh = __float2half_rn(b);
    __half al = __float2half_rn(a - __half2float(ah));
    __half bl = __float2half_rn(b - __half2float(bh));
    h = (u32)__half_as_ushort(ah) | ((u32)__half_as_ushort(bh) << 16);
    l = (u32)__half_as_ushort(al) | ((u32)__half_as_ushort(bl) << 16);
}

// =============================================================
// shared swizzle: 64B rows, 16B chunks
// =============================================================
#define KC 32
#define STAGES 3

__device__ __forceinline__ u32 sw32(int row, int chunk) {
    u32 off = (u32)row * 64u + (u32)chunk * 16u;
    return off ^ ((((u32)row >> 1) & 7u) << 4);
}
__device__ __forceinline__ u32 lm_addr(u32 tile, int row, int ks, int khalf) {
    return tile + sw32(row, (ks << 1) | khalf);
}

// =============================================================
// bf16x2 3-term GEMM (NT). OUT: 0 = fp32 C, 2 = fused QKV routing.
// Block tile 128x128, 8 warps (2x4), warp tile 64x32.
// =============================================================
template <int OUT>
__global__ __launch_bounds__(256, 2) void gemm_mma(
    const u16* __restrict__ Ah, const u16* __restrict__ Al,
    const u16* __restrict__ Bh, const u16* __restrict__ Bl,
    float* __restrict__ Cf, u16* __restrict__ Ch, u16* __restrict__ Cl,
    u16* __restrict__ Ch2, u16* __restrict__ Cl2,
    int M, int N, int K,
    size_t sA, size_t sB, size_t sC, float alpha)
{
    constexpr int TILEA  = 128 * 64;
    constexpr int TILEBB = 128 * 64;
    constexpr int BUF    = 2 * TILEA + 2 * TILEBB;

    extern __shared__ __align__(1024) char smem[];
    const u32 sb = s2u(smem);
    const int tid  = threadIdx.x;
    const int lane = tid & 31;
    const int warp = tid >> 5;

    Ah += (size_t)blockIdx.z * sA;  Al += (size_t)blockIdx.z * sA;
    Bh += (size_t)blockIdx.z * sB;  Bl += (size_t)blockIdx.z * sB;

    const int row0 = blockIdx.y * 128;
    const int col0 = blockIdx.x * 128;

    const int warpM = (warp >> 2) * 64;
    const int warpN = (warp & 3) * 32;
    const int lrow  = lane & 15;
    const int khalf = lane >> 4;

    // staging: 2 thr/row, 2 x 16B chunks each (A and B both 128 rows)
    const int r    = tid >> 1;
    const int hf   = tid & 1;
    const u32 sw0 = sw32(r, 2 * hf);
    const u32 sw1 = sw32(r, 2 * hf + 1);
    const u16* gAh = Ah + (size_t)(row0 + r) * K + hf * 16;
    const u16* gAl = Al + (size_t)(row0 + r) * K + hf * 16;
    const u16* gBh = Bh + (size_t)(col0 + r) * K + hf * 16;
    const u16* gBl = Bl + (size_t)(col0 + r) * K + hf * 16;

    const int nC = K / KC;

    auto load_chunk = [&](int c, int slot) {
        const u32 tb = sb + (u32)slot * BUF;
        const int ko = c * KC;
        cpasync16(tb + sw0, gAh + ko);
        cpasync16(tb + sw1, gAh + ko + 8);
        cpasync16(tb + TILEA + sw0, gAl + ko);
        cpasync16(tb + TILEA + sw1, gAl + ko + 8);
        const u32 tbB = tb + 2 * TILEA;
        cpasync16(tbB + sw0, gBh + ko);
        cpasync16(tbB + sw1, gBh + ko + 8);
        cpasync16(tbB + TILEBB + sw0, gBl + ko);
        cpasync16(tbB + TILEBB + sw1, gBl + ko + 8);
    };

    float acc[4][4][4] = {};

    load_chunk(0, 0); cp_commit();
    load_chunk(1, 1); cp_commit();

    for (int c = 0; c < nC; c++) {
        const int slot = c % STAGES;

        cp_wait<1>();
        __syncthreads();

        if (c + 2 < nC)
            load_chunk(c + 2, (c + 2) % STAGES);
        cp_commit();

        const u32 tAh = sb + (u32)slot * BUF;
        const u32 tAl = tAh + TILEA;
        const u32 tBh = tAh + 2 * TILEA;
        const u32 tBl = tBh + TILEBB;

#pragma unroll
        for (int ks = 0; ks < 2; ks++) {
            u32 bh[4][2], bl[4][2];
#pragma unroll
            for (int h = 0; h < 2; h++) {
                const int rowB = warpN + h * 16 + lrow;
                u32 r0, r1, r2, r3;
                ldm_x4(lm_addr(tBh, rowB, ks, khalf), r0, r1, r2, r3);
                bh[2*h][0] = r0; bh[2*h+1][0] = r1;
                bh[2*h][1] = r2; bh[2*h+1][1] = r3;
                ldm_x4(lm_addr(tBl, rowB, ks, khalf), r0, r1, r2, r3);
                bl[2*h][0] = r0; bl[2*h+1][0] = r1;
                bl[2*h][1] = r2; bl[2*h+1][1] = r3;
            }
#pragma unroll
            for (int mi = 0; mi < 4; mi++) {
                const int rowA = warpM + mi * 16 + lrow;
                u32 ah[4], al[4];
                ldm_x4(lm_addr(tAh, rowA, ks, khalf), ah[0], ah[1], ah[2], ah[3]);
                ldm_x4(lm_addr(tAl, rowA, ks, khalf), al[0], al[1], al[2], al[3]);
#pragma unroll
                for (int ni = 0; ni < 4; ni++) {
                    mma_bf16(acc[mi][ni], ah, bh[ni]);
                    mma_bf16(acc[mi][ni], ah, bl[ni]);
                    mma_bf16(acc[mi][ni], al, bh[ni]);
                }
            }
        }
    }

    // ---- epilogue ----
    const int g  = lane >> 2;
    const int tc = (lane & 3) * 2;

    int seg = 0, lcol = col0;
    if (OUT == 2) { seg = col0 / 768; lcol = col0 - seg * 768; }
    const int ostride = (OUT == 2) ? 768 : N;

#pragma unroll
    for (int mi = 0; mi < 4; mi++) {
#pragma unroll
        for (int h = 0; h < 2; h++) {
            const int row = row0 + warpM + mi * 16 + g + h * 8;
            const size_t ob = (size_t)blockIdx.z * sC + (size_t)row * ostride + lcol + warpN;
            if (OUT == 0) {
#pragma unroll
                for (int ni = 0; ni < 4; ni++) {
                    float2 v = make_float2(alpha * acc[mi][ni][h*2],
                                           alpha * acc[mi][ni][h*2+1]);
                    *(float2*)(Cf + ob + ni * 8 + tc) = v;
                }
            } else {  // OUT == 2, QKV routing
                if (seg == 2) {
#pragma unroll
                    for (int ni = 0; ni < 4; ni++) {
                        float2 v = make_float2(acc[mi][ni][h*2], acc[mi][ni][h*2+1]);
                        *(float2*)(Cf + ob + ni * 8 + tc) = v;
                    }
                } else {
                    u16* oh = (seg == 0) ? Ch : Ch2;
                    u16* ol = (seg == 0) ? Cl : Cl2;
#pragma unroll
                    for (int ni = 0; ni < 4; ni++) {
                        u32 hh, ll;
                        split2(acc[mi][ni][h*2], acc[mi][ni][h*2+1], hh, ll);
                        *(u32*)(oh + ob + ni * 8 + tc) = hh;
                        *(u32*)(ol + ob + ni * 8 + tc) = ll;
                    }
                }
            }
        }
    }
}

// =============================================================
// fp16 2-term AV GEMM (NT): C = A[M,K] * B[N,K]^T
// A = P split hi/lo fp16; B = V^T hi fp16 only.
// Block tile 64x128, 8 warps (2x4), warp tile 32x32 (MIA=2).
// acc += ah*bh + al*bh   (dropped ah*bl ~ 2^-12 rel)
// =============================================================
__global__ __launch_bounds__(256, 2) void gemm_av(
    const u16* __restrict__ Ah, const u16* __restrict__ Al,
    const u16* __restrict__ Bh,
    float* __restrict__ Cf,
    int M, int N, int K,
    size_t sA, size_t sB, size_t sC)
{
    constexpr int TILEA  = 64 * 64;    // 4 KB per A array
    constexpr int TILEBB = 128 * 64;   // 8 KB
    constexpr int BUF    = 2 * TILEA + TILEBB;  // 16 KB

    extern __shared__ __align__(1024) char smem[];
    const u32 sb = s2u(smem);
    const int tid  = threadIdx.x;
    const int lane = tid & 31;
    const int warp = tid >> 5;

    Ah += (size_t)blockIdx.z * sA;  Al += (size_t)blockIdx.z * sA;
    Bh += (size_t)blockIdx.z * sB;

    const int row0 = blockIdx.y * 64;
    const int col0 = blockIdx.x * 128;

    const int warpM = (warp >> 2) * 32;
    const int warpN = (warp & 3) * 32;
    const int lrow  = lane & 15;
    const int khalf = lane >> 4;

    // A: 64 rows, 4 thr/row, 1 x 16B chunk each
    const int rA = tid >> 2;
    const int cA = tid & 3;
    const u32 swA = sw32(rA, cA);
    const u16* gAh = Ah + (size_t)(row0 + rA) * K + cA * 8;
    const u16* gAl = Al + (size_t)(row0 + rA) * K + cA * 8;
    // B: 128 rows, 2 thr/row, 2 x 16B chunks each
    const int rB = tid >> 1;
    const int hB = tid & 1;
    const u32 swB0 = sw32(rB, 2 * hB);
    const u32 swB1 = sw32(rB, 2 * hB + 1);
    const u16* gBh = Bh + (size_t)(col0 + rB) * K + hB * 16;

    const int nC = K / KC;

    auto load_chunk = [&](int c, int slot) {
        const u32 tb = sb + (u32)slot * BUF;
        const int ko = c * KC;
        cpasync16(tb + swA, gAh + ko);
        cpasync16(tb + TILEA + swA, gAl + ko);
        const u32 tbB = tb + 2 * TILEA;
        cpasync16(tbB + swB0, gBh + ko);
        cpasync16(tbB + swB1, gBh + ko + 8);
    };

    float acc[2][4][4] = {};

    load_chunk(0, 0); cp_commit();
    load_chunk(1, 1); cp_commit();

    for (int c = 0; c < nC; c++) {
        const int slot = c % STAGES;

        cp_wait<1>();
        __syncthreads();

        if (c + 2 < nC)
            load_chunk(c + 2, (c + 2) % STAGES);
        cp_commit();

        const u32 tAh = sb + (u32)slot * BUF;
        const u32 tAl = tAh + TILEA;
        const u32 tBh = tAh + 2 * TILEA;

#pragma unroll
        for (int ks = 0; ks < 2; ks++) {
            u32 bh[4][2];
#pragma unroll
            for (int h = 0; h < 2; h++) {
                const int rowB = warpN + h * 16 + lrow;
                u32 r0, r1, r2, r3;
                ldm_x4(lm_addr(tBh, rowB, ks, khalf), r0, r1, r2, r3);
                bh[2*h][0] = r0; bh[2*h+1][0] = r1;
                bh[2*h][1] = r2; bh[2*h+1][1] = r3;
            }
#pragma unroll
            for (int mi = 0; mi < 2; mi++) {
                const int rowA = warpM + mi * 16 + lrow;
                u32 ah[4], al[4];
                ldm_x4(lm_addr(tAh, rowA, ks, khalf), ah[0], ah[1], ah[2], ah[3]);
                ldm_x4(lm_addr(tAl, rowA, ks, khalf), al[0], al[1], al[2], al[3]);
#pragma unroll
                for (int ni = 0; ni < 4; ni++) {
                    mma_f16(acc[mi][ni], ah, bh[ni]);
                    mma_f16(acc[mi][ni], al, bh[ni]);
                }
            }
        }
    }

    const int g  = lane >> 2;
    const int tc = (lane & 3) * 2;
#pragma unroll
    for (int mi = 0; mi < 2; mi++) {
#pragma unroll
        for (int h = 0; h < 2; h++) {
            const int row = row0 + warpM + mi * 16 + g + h * 8;
            float* crow = Cf + (size_t)blockIdx.z * sC + (size_t)row * N + col0 + warpN;
#pragma unroll
            for (int ni = 0; ni < 4; ni++) {
                float2 v = make_float2(acc[mi][ni][h*2], acc[mi][ni][h*2+1]);
                *(float2*)(crow + ni * 8 + tc) = v;
            }
        }
    }
}

// ---------------- fp32 -> split bf16 (elementwise) ----------------
__global__ __launch_bounds__(256) void convert_split(
    const float* __restrict__ in, u16* __restrict__ hi, u16* __restrict__ lo, size_t n)
{
    size_t i = ((size_t)blockIdx.x * blockDim.x + threadIdx.x) * 4;
    if (i >= n) return;
    float4 v = *(const float4*)(in + i);
    u32 h0, l0, h1, l1;
    split2(v.x, v.y, h0, l0);
    split2(v.z, v.w, h1, l1);
    *(uint2*)(hi + i) = make_uint2(h0, h1);
    *(uint2*)(lo + i) = make_uint2(l0, l1);
}

// ---------------- transpose + split bf16 convert (weights) ----------------
__global__ __launch_bounds__(256) void transpose_convert(
    const float* __restrict__ in, u16* __restrict__ oh, u16* __restrict__ ol,
    int R, int C)
{
    __shared__ float t[32][33];
    in += (size_t)blockIdx.z * R * C;
    oh += (size_t)blockIdx.z * R * C;
    ol += (size_t)blockIdx.z * R * C;
    const int c0 = blockIdx.x * 32, r0 = blockIdx.y * 32;
    const int tx = threadIdx.x & 31, ty = threadIdx.x >> 5;
#pragma unroll
    for (int j = 0; j < 32; j += 8)
        t[ty + j][tx] = in[(size_t)(r0 + ty + j) * C + c0 + tx];
    __syncthreads();
#pragma unroll
    for (int j = 0; j < 32; j += 8) {
        float v = t[tx][ty + j];
        __nv_bfloat16 h = __float2bfloat16_rn(v);
        __nv_bfloat16 l = __float2bfloat16_rn(v - __bfloat162float(h));
        size_t o = (size_t)(c0 + ty + j) * R + r0 + tx;
        oh[o] = __bfloat16_as_ushort(h);
        ol[o] = __bfloat16_as_ushort(l);
    }
}

// ---------------- transpose + fp16-hi convert (V) ----------------
__global__ __launch_bounds__(256) void transpose_convert_h(
    const float* __restrict__ in, u16* __restrict__ oh, int R, int C)
{
    __shared__ float t[32][33];
    in += (size_t)blockIdx.z * R * C;
    oh += (size_t)blockIdx.z * R * C;
    const int c0 = blockIdx.x * 32, r0 = blockIdx.y * 32;
    const int tx = threadIdx.x & 31, ty = threadIdx.x >> 5;
#pragma unroll
    for (int j = 0; j < 32; j += 8)
        t[ty + j][tx] = in[(size_t)(r0 + ty + j) * C + c0 + tx];
    __syncthreads();
#pragma unroll
    for (int j = 0; j < 32; j += 8) {
        float v = t[tx][ty + j];
        size_t o = (size_t)(c0 + ty + j) * R + r0 + tx;
        oh[o] = __half_as_ushort(__float2half_rn(v));
    }
}

// ---------------- row softmax: fp32 in, split fp16 out ----------------
__global__ __launch_bounds__(256) void softmax_kernel(
    const float* __restrict__ S, u16* __restrict__ Ph, u16* __restrict__ Pl)
{
    const size_t base = (size_t)blockIdx.x * SS;
    const int tid = threadIdx.x;
    __shared__ float red[32];

    float4 v0 = *(const float4*)(S + base + tid * 8);
    float4 v1 = *(const float4*)(S + base + tid * 8 + 4);

    float m = fmaxf(fmaxf(fmaxf(v0.x, v0.y), fmaxf(v0.z, v0.w)),
                    fmaxf(fmaxf(v1.x, v1.y), fmaxf(v1.z, v1.w)));
#pragma unroll
    for (int s = 16; s > 0; s >>= 1)
        m = fmaxf(m, __shfl_xor_sync(0xffffffff, m, s));
    if ((tid & 31) == 0) red[tid >> 5] = m;
    __syncthreads();
    {
        float t = red[tid & 7];
#pragma unroll
        for (int s = 4; s > 0; s >>= 1)
            t = fmaxf(t, __shfl_xor_sync(0xffffffff, t, s));
        m = t;
    }

    v0.x = __expf(v0.x - m); v0.y = __expf(v0.y - m);
    v0.z = __expf(v0.z - m); v0.w = __expf(v0.w - m);
    v1.x = __expf(v1.x - m); v1.y = __expf(v1.y - m);
    v1.z = __expf(v1.z - m); v1.w = __expf(v1.w - m);
    float sum = v0.x + v0.y + v0.z + v0.w + v1.x + v1.y + v1.z + v1.w;
#pragma unroll
    for (int s = 16; s > 0; s >>= 1)
        sum += __shfl_xor_sync(0xffffffff, sum, s);
    __syncthreads();
    if ((tid & 31) == 0) red[tid >> 5] = sum;
    __syncthreads();
    {
        float t = red[tid & 7];
#pragma unroll
        for (int s = 4; s > 0; s >>= 1)
            t += __shfl_xor_sync(0xffffffff, t, s);
        sum = t;
    }

    const float inv = 1.0f / sum;
    float f[8] = {v0.x * inv, v0.y * inv, v0.z * inv, v0.w * inv,
                  v1.x * inv, v1.y * inv, v1.z * inv, v1.w * inv};
    u32 h[4], l[4];
#pragma unroll
    for (int p = 0; p < 4; p++)
        split2h(f[p*2], f[p*2+1], h[p], l[p]);
    *(uint4*)(Ph + base + tid * 8) = make_uint4(h[0], h[1], h[2], h[3]);
    *(uint4*)(Pl + base + tid * 8) = make_uint4(l[0], l[1], l[2], l[3]);
}

// ---------------- launch ----------------
extern "C" void kernel_launch(void* const* d_in, const int* in_sizes, int n_in,
                              void* d_out, int out_size)
{
    const float* x   = (const float*)d_in[0];
    const float* W_q = (const float*)d_in[1];
    const float* W_k = (const float*)d_in[2];
    const float* W_v = (const float*)d_in[3];
    float* out = (float*)d_out;

    u16 *xh, *xl, *Wth, *Wtl, *Qh, *Ql, *Kh, *Kl, *Vth, *Ph, *Pl;
    float *V, *Sc;
    cudaGetSymbolAddress((void**)&xh,  g_xh);
    cudaGetSymbolAddress((void**)&xl,  g_xl);
    cudaGetSymbolAddress((void**)&Wth, g_Wth);
    cudaGetSymbolAddress((void**)&Wtl, g_Wtl);
    cudaGetSymbolAddress((void**)&Qh,  g_Qh);
    cudaGetSymbolAddress((void**)&Ql,  g_Ql);
    cudaGetSymbolAddress((void**)&Kh,  g_Kh);
    cudaGetSymbolAddress((void**)&Kl,  g_Kl);
    cudaGetSymbolAddress((void**)&V,   g_V);
    cudaGetSymbolAddress((void**)&Vth, g_Vth);
    cudaGetSymbolAddress((void**)&Sc,  g_S);
    cudaGetSymbolAddress((void**)&Ph,  g_Ph);
    cudaGetSymbolAddress((void**)&Pl,  g_Pl);

    const int SM128 = STAGES * (2 * 128 * 64 + 2 * 128 * 64);  // 98304
    const int SMAV  = STAGES * (2 * 64 * 64 + 128 * 64);       // 49152
    cudaFuncSetAttribute(gemm_mma<0>, cudaFuncAttributeMaxDynamicSharedMemorySize, SM128);
    cudaFuncSetAttribute(gemm_mma<2>, cudaFuncAttributeMaxDynamicSharedMemorySize, SM128);
    cudaFuncSetAttribute(gemm_av,     cudaFuncAttributeMaxDynamicSharedMemorySize, SMAV);

    const int M1 = BB * SS;  // 8192
    const float scale = 1.0f / sqrtf((float)UU);
    const size_t WSZ = (size_t)DD * UU;

    // 0) convert x -> split bf16
    {
        size_t n = (size_t)M1 * DD;
        convert_split<<<(unsigned)((n / 4 + 255) / 256), 256>>>(x, xh, xl, n);
    }
    // 0b) transpose+convert weights: stacked [Wq^T; Wk^T; Wv^T]
    {
        dim3 g(UU / 32, DD / 32, 1);
        transpose_convert<<<g, 256>>>(W_q, Wth + 0 * WSZ, Wtl + 0 * WSZ, DD, UU);
        transpose_convert<<<g, 256>>>(W_k, Wth + 1 * WSZ, Wtl + 1 * WSZ, DD, UU);
        transpose_convert<<<g, 256>>>(W_v, Wth + 2 * WSZ, Wtl + 2 * WSZ, DD, UU);
    }

    // 1) fused QKV projection: routes Q,K -> split bf16, V -> fp32
    {
        dim3 g(3 * UU / 128, M1 / 128, 1);
        gemm_mma<2><<<g, 256, SM128>>>(xh, xl, Wth, Wtl,
                                       V, Qh, Ql, Kh, Kl,
                                       M1, 3 * UU, DD, 0, 0, 0, 1.0f);
    }

    // 2) transpose V per batch -> fp16 hi only: Vt[b][u][s]
    {
        dim3 g(UU / 32, SS / 32, BB);
        transpose_convert_h<<<g, 256>>>(V, Vth, SS, UU);
    }

    // 3) scores = scale * Q K^T  -> fp32
    {
        dim3 g(SS / 128, SS / 128, BB);
        gemm_mma<0><<<g, 256, SM128>>>(Qh, Ql, Kh, Kl, Sc, nullptr, nullptr, nullptr, nullptr,
                                       SS, SS, UU,
                                       (size_t)SS * UU, (size_t)SS * UU, (size_t)SS * SS,
                                       scale);
    }

    // 4) softmax rows -> split fp16 attn
    softmax_kernel<<<BB * SS, 256>>>(Sc, Ph, Pl);

    // 5) out = attn * Vt (NT), fp16 2-term
    {
        dim3 g(UU / 128, SS / 64, BB);
        gemm_av<<<g, 256, SMAV>>>(Ph, Pl, Vth, out,
                                  SS, UU, SS,
                                  (size_t)SS * SS, (size_t)SS * UU, (size_t)SS * UU);
    }
}